// round 6
// baseline (speedup 1.0000x reference)
#include <cuda_runtime.h>
#include <cuda_fp16.h>

#define NN   50000
#define ER   1600000
#define EMB  32
#define HID  128
#define TILE 64

typedef unsigned long long u64;

// ---- packed f32x2 helpers (sm_103a FFMA2 path, PTX-only) ----
__device__ __forceinline__ u64 dup2(float a) {
    u64 r; asm("mov.b64 %0, {%1, %1};" : "=l"(r) : "f"(a)); return r;
}
__device__ __forceinline__ u64 packf2(float a, float b) {
    u64 r; asm("mov.b64 %0, {%1, %2};" : "=l"(r) : "f"(a), "f"(b)); return r;
}
__device__ __forceinline__ void ffma2(u64& d, u64 a, u64 b) {
    asm("fma.rn.f32x2 %0, %1, %2, %0;" : "+l"(d) : "l"(a), "l"(b));
}
__device__ __forceinline__ float2 unpackf2(u64 v) {
    float2 r; asm("mov.b64 {%0, %1}, %2;" : "=f"(r.x), "=f"(r.y) : "l"(v)); return r;
}

// fp16x4 (as uint2) multiply-accumulate into float4, weight scalar
__device__ __forceinline__ void acc16(float4& acc, uint2 u, float wgt) {
    float2 ul = __half22float2(*reinterpret_cast<__half2*>(&u.x));
    float2 uh = __half22float2(*reinterpret_cast<__half2*>(&u.y));
    acc.x += ul.x * wgt; acc.y += ul.y * wgt;
    acc.z += uh.x * wgt; acc.w += uh.y * wgt;
}

// ---------------- device scratch (static, no cudaMalloc) ----------------
__device__ int    g_deg[NN];
__device__ float  g_dinv[NN];
__device__ int    g_rowstart[NN];
__device__ int    g_cursor[NN];
__device__ int    g_col[ER];             // 6.4 MB
__device__ int    g_total;
__device__ __half g_h1h[NN * HID];       // 12.8 MB (fp16 hidden)

// ---------------- 1) init ----------------
__global__ void k_init() {
    int i = blockIdx.x * 256 + threadIdx.x;
    if (i < NN) g_deg[i] = 1;
    if (i == 0) g_total = 0;
}

// ---------------- 2) degree histogram over dst (2 edges/thread) ----------------
__global__ void k_deg(const int* __restrict__ ei) {
    int t = blockIdx.x * 256 + threadIdx.x;          // t < ER/2
    int2 d2 = reinterpret_cast<const int2*>(ei + ER)[t];
    atomicAdd(&g_deg[d2.x], 1);
    atomicAdd(&g_deg[d2.y], 1);
}

// ---------------- 3) dinv + CSR row allocation (warp-aggregated bump) ----------------
__global__ void k_dinv_alloc() {
    int i    = blockIdx.x * 256 + threadIdx.x;
    int lane = threadIdx.x & 31;
    int cnt  = 0;
    if (i < NN) {
        int d = g_deg[i];
        g_dinv[i] = rsqrtf((float)d);
        cnt = d - 1;
    }
    int incl = cnt;
#pragma unroll
    for (int off = 1; off < 32; off <<= 1) {
        int t = __shfl_up_sync(0xffffffffu, incl, off);
        if (lane >= off) incl += t;
    }
    int total = __shfl_sync(0xffffffffu, incl, 31);
    int base  = 0;
    if (lane == 31) base = atomicAdd(&g_total, total);
    base = __shfl_sync(0xffffffffu, base, 31);
    if (i < NN) {
        int start = base + incl - cnt;
        g_rowstart[i] = start;
        g_cursor[i]   = start;
    }
}

// ---------------- 4) scatter edges into CSR buckets (lean, 2 edges/thread) ----------------
__global__ void k_scatter(const int* __restrict__ ei) {
    int t = blockIdx.x * 256 + threadIdx.x;          // t < ER/2
    int2 s2 = reinterpret_cast<const int2*>(ei)[t];
    int2 d2 = reinterpret_cast<const int2*>(ei + ER)[t];
    int p0 = atomicAdd(&g_cursor[d2.x], 1);
    int p1 = atomicAdd(&g_cursor[d2.y], 1);
    g_col[p0] = s2.x;
    g_col[p1] = s2.y;
}

// ---------------- 5) FUSED layer 1: agg(emb) + GEMM1 + relu -> h1 fp16 ----------------
__global__ void __launch_bounds__(256) k_fused1(const float* __restrict__ emb,
                                                const float* __restrict__ W1,
                                                const float* __restrict__ b1) {
    __shared__ float As[TILE * EMB];     // 8 KB
    int tid  = threadIdx.x;
    int lane = tid & 31;
    int wid  = tid >> 5;
    int tcol = (tid & 15) * 8;           // 0..120
    int trow = (tid >> 4) * 4;           // 0..60
    u64 bias[4];
    bias[0] = packf2(__ldg(&b1[tcol]),     __ldg(&b1[tcol + 1]));
    bias[1] = packf2(__ldg(&b1[tcol + 2]), __ldg(&b1[tcol + 3]));
    bias[2] = packf2(__ldg(&b1[tcol + 4]), __ldg(&b1[tcol + 5]));
    bias[3] = packf2(__ldg(&b1[tcol + 6]), __ldg(&b1[tcol + 7]));

    const int NT = (NN + TILE - 1) / TILE;           // 782
    for (int t = blockIdx.x; t < NT; t += gridDim.x) {
        int row0 = t * TILE;
        __syncthreads();                 // protect As from previous tile's readers
        // ---- phase A: each warp aggregates 8 nodes (lane = emb dim) ----
        for (int j = 0; j < 8; j++) {
            int lr = wid * 8 + j;
            int n  = row0 + lr;
            float acc = 0.f;
            if (n < NN) {
                float di = g_dinv[n];
                acc = __ldcs(&emb[n * EMB + lane]) * (di * di);   // self loop
                int start = g_rowstart[n], cnt = g_deg[n] - 1, e = 0;
                for (; e + 4 <= cnt; e += 4) {
                    int s0 = __ldcs(&g_col[start + e]);
                    int s1 = __ldcs(&g_col[start + e + 1]);
                    int s2 = __ldcs(&g_col[start + e + 2]);
                    int s3 = __ldcs(&g_col[start + e + 3]);
                    float r0 = __ldcs(&emb[s0 * EMB + lane]);
                    float r1 = __ldcs(&emb[s1 * EMB + lane]);
                    float r2 = __ldcs(&emb[s2 * EMB + lane]);
                    float r3 = __ldcs(&emb[s3 * EMB + lane]);
                    acc += r0 * (g_dinv[s0] * di);
                    acc += r1 * (g_dinv[s1] * di);
                    acc += r2 * (g_dinv[s2] * di);
                    acc += r3 * (g_dinv[s3] * di);
                }
                for (; e < cnt; e++) {
                    int s = __ldcs(&g_col[start + e]);
                    acc += __ldcs(&emb[s * EMB + lane]) * (g_dinv[s] * di);
                }
            }
            As[lr * EMB + lane] = acc;
        }
        __syncthreads();
        // ---- phase B: 64x32x128 GEMM, 4 rows x 8 cols per thread, FFMA2 ----
        u64 acc[4][4];
#pragma unroll
        for (int r = 0; r < 4; r++)
#pragma unroll
            for (int c = 0; c < 4; c++) acc[r][c] = bias[c];
#pragma unroll
        for (int k = 0; k < EMB; k++) {
            ulonglong2 wa = __ldg(reinterpret_cast<const ulonglong2*>(&W1[k * HID + tcol]));
            ulonglong2 wb = __ldg(reinterpret_cast<const ulonglong2*>(&W1[k * HID + tcol + 4]));
#pragma unroll
            for (int r = 0; r < 4; r++) {
                u64 a = dup2(As[(trow + r) * EMB + k]);
                ffma2(acc[r][0], a, wa.x); ffma2(acc[r][1], a, wa.y);
                ffma2(acc[r][2], a, wb.x); ffma2(acc[r][3], a, wb.y);
            }
        }
#pragma unroll
        for (int r = 0; r < 4; r++) {
            int gr = row0 + trow + r;
            if (gr < NN) {
                float2 p0 = unpackf2(acc[r][0]);
                float2 p1 = unpackf2(acc[r][1]);
                float2 p2 = unpackf2(acc[r][2]);
                float2 p3 = unpackf2(acc[r][3]);
                __half2 h0 = __floats2half2_rn(fmaxf(p0.x, 0.f), fmaxf(p0.y, 0.f));
                __half2 h1 = __floats2half2_rn(fmaxf(p1.x, 0.f), fmaxf(p1.y, 0.f));
                __half2 h2 = __floats2half2_rn(fmaxf(p2.x, 0.f), fmaxf(p2.y, 0.f));
                __half2 h3 = __floats2half2_rn(fmaxf(p3.x, 0.f), fmaxf(p3.y, 0.f));
                uint4 st;
                st.x = *reinterpret_cast<unsigned*>(&h0);
                st.y = *reinterpret_cast<unsigned*>(&h1);
                st.z = *reinterpret_cast<unsigned*>(&h2);
                st.w = *reinterpret_cast<unsigned*>(&h3);
                *reinterpret_cast<uint4*>(&g_h1h[gr * HID + tcol]) = st;
            }
        }
    }
}

// ---------------- 6) FUSED layer 2: agg(h1) + GEMM2 -> out ----------------
__global__ void __launch_bounds__(256, 3) k_fused2(const float* __restrict__ W2,
                                                   const float* __restrict__ b2,
                                                   float* __restrict__ out) {
    __shared__ float As[TILE * HID];     // 32 KB
    int tid  = threadIdx.x;
    int lane = tid & 31;
    int wid  = tid >> 5;
    int tcol = (tid & 15) * 8;           // 0..120
    int trow = (tid >> 4) * 4;           // 0..60
    u64 bias[4];
    bias[0] = packf2(__ldg(&b2[tcol]),     __ldg(&b2[tcol + 1]));
    bias[1] = packf2(__ldg(&b2[tcol + 2]), __ldg(&b2[tcol + 3]));
    bias[2] = packf2(__ldg(&b2[tcol + 4]), __ldg(&b2[tcol + 5]));
    bias[3] = packf2(__ldg(&b2[tcol + 6]), __ldg(&b2[tcol + 7]));

    const uint2* hv = reinterpret_cast<const uint2*>(g_h1h);   // 4 halves / uint2

    const int NT = (NN + TILE - 1) / TILE;           // 782
    for (int t = blockIdx.x; t < NT; t += gridDim.x) {
        int row0 = t * TILE;
        __syncthreads();
        // ---- phase A: each warp aggregates 8 nodes (128-dim fp16 -> fp32) ----
        for (int j = 0; j < 8; j++) {
            int lr = wid * 8 + j;
            int n  = row0 + lr;
            float4 acc = make_float4(0.f, 0.f, 0.f, 0.f);
            if (n < NN) {
                float di = g_dinv[n];
                uint2 v  = hv[n * 32 + lane];
                float2 vl = __half22float2(*reinterpret_cast<__half2*>(&v.x));
                float2 vh = __half22float2(*reinterpret_cast<__half2*>(&v.y));
                float sw = di * di;
                acc = make_float4(vl.x * sw, vl.y * sw, vh.x * sw, vh.y * sw);
                int start = g_rowstart[n], cnt = g_deg[n] - 1, e = 0;
                for (; e + 4 <= cnt; e += 4) {
                    int s0 = __ldcs(&g_col[start + e]);
                    int s1 = __ldcs(&g_col[start + e + 1]);
                    int s2 = __ldcs(&g_col[start + e + 2]);
                    int s3 = __ldcs(&g_col[start + e + 3]);
                    uint2 u0 = __ldcs(&hv[s0 * 32 + lane]);
                    uint2 u1 = __ldcs(&hv[s1 * 32 + lane]);
                    uint2 u2 = __ldcs(&hv[s2 * 32 + lane]);
                    uint2 u3 = __ldcs(&hv[s3 * 32 + lane]);
                    acc16(acc, u0, g_dinv[s0] * di);
                    acc16(acc, u1, g_dinv[s1] * di);
                    acc16(acc, u2, g_dinv[s2] * di);
                    acc16(acc, u3, g_dinv[s3] * di);
                }
                for (; e < cnt; e++) {
                    int s = __ldcs(&g_col[start + e]);
                    uint2 u = __ldcs(&hv[s * 32 + lane]);
                    acc16(acc, u, g_dinv[s] * di);
                }
            }
            reinterpret_cast<float4*>(As)[lr * 32 + lane] = acc;
        }
        __syncthreads();
        // ---- phase B: 64x128x128 GEMM, 4 rows x 8 cols per thread, FFMA2 ----
        u64 acc[4][4];
#pragma unroll
        for (int r = 0; r < 4; r++)
#pragma unroll
            for (int c = 0; c < 4; c++) acc[r][c] = bias[c];
#pragma unroll 4
        for (int k = 0; k < HID; k++) {
            ulonglong2 wa = __ldg(reinterpret_cast<const ulonglong2*>(&W2[k * HID + tcol]));
            ulonglong2 wb = __ldg(reinterpret_cast<const ulonglong2*>(&W2[k * HID + tcol + 4]));
#pragma unroll
            for (int r = 0; r < 4; r++) {
                u64 a = dup2(As[(trow + r) * HID + k]);
                ffma2(acc[r][0], a, wa.x); ffma2(acc[r][1], a, wa.y);
                ffma2(acc[r][2], a, wb.x); ffma2(acc[r][3], a, wb.y);
            }
        }
#pragma unroll
        for (int r = 0; r < 4; r++) {
            int gr = row0 + trow + r;
            if (gr < NN) {
                float2 p0 = unpackf2(acc[r][0]);
                float2 p1 = unpackf2(acc[r][1]);
                float2 p2 = unpackf2(acc[r][2]);
                float2 p3 = unpackf2(acc[r][3]);
                *reinterpret_cast<float4*>(&out[gr * HID + tcol])     = make_float4(p0.x, p0.y, p1.x, p1.y);
                *reinterpret_cast<float4*>(&out[gr * HID + tcol + 4]) = make_float4(p2.x, p2.y, p3.x, p3.y);
            }
        }
    }
}

// ---------------- host launcher ----------------
extern "C" void kernel_launch(void* const* d_in, const int* in_sizes, int n_in,
                              void* d_out, int out_size) {
    const int*   ei  = (const int*)d_in[1];
    const float* emb = (const float*)d_in[2];
    const float* W1  = (const float*)d_in[3];
    const float* b1  = (const float*)d_in[4];
    const float* W2  = (const float*)d_in[5];
    const float* b2  = (const float*)d_in[6];
    float* out = (float*)d_out;

    k_init      <<<(NN + 255) / 256, 256>>>();
    k_deg       <<<ER / 2 / 256, 256>>>(ei);
    k_dinv_alloc<<<(NN + 255) / 256, 256>>>();
    k_scatter   <<<ER / 2 / 256, 256>>>(ei);
    k_fused1    <<<1184, 256>>>(emb, W1, b1);
    k_fused2    <<<444, 256>>>(W2, b2, out);
}

// round 7
// speedup vs baseline: 1.1307x; 1.1307x over previous
#include <cuda_runtime.h>
#include <cuda_fp16.h>

#define NN   50000
#define ER   1600000
#define EMB  32
#define HID  128
#define TILE 64

typedef unsigned long long u64;

// ---- packed f32x2 helpers (sm_103a FFMA2 path, PTX-only) ----
__device__ __forceinline__ u64 dup2(float a) {
    u64 r; asm("mov.b64 %0, {%1, %1};" : "=l"(r) : "f"(a)); return r;
}
__device__ __forceinline__ u64 packf2(float a, float b) {
    u64 r; asm("mov.b64 %0, {%1, %2};" : "=l"(r) : "f"(a), "f"(b)); return r;
}
__device__ __forceinline__ void ffma2(u64& d, u64 a, u64 b) {
    asm("fma.rn.f32x2 %0, %1, %2, %0;" : "+l"(d) : "l"(a), "l"(b));
}
__device__ __forceinline__ float2 unpackf2(u64 v) {
    float2 r; asm("mov.b64 {%0, %1}, %2;" : "=f"(r.x), "=f"(r.y) : "l"(v)); return r;
}

// fp16x4 (as uint2) multiply-accumulate into float4
__device__ __forceinline__ void acc16(float4& acc, uint2 u, float wgt) {
    float2 ul = __half22float2(*reinterpret_cast<__half2*>(&u.x));
    float2 uh = __half22float2(*reinterpret_cast<__half2*>(&u.y));
    acc.x += ul.x * wgt; acc.y += ul.y * wgt;
    acc.z += uh.x * wgt; acc.w += uh.y * wgt;
}

// ---------------- device scratch (static, no cudaMalloc) ----------------
__device__ int    g_deg[NN];
__device__ float  g_dinv[NN];
__device__ int    g_rowstart[NN];
__device__ int    g_cursor[NN];
__device__ int    g_col[ER];             //  6.4 MB
__device__ int    g_total;
__device__ float  g_aggemb[NN * EMB];    //  6.4 MB
__device__ __half g_h1h[NN * HID];       // 12.8 MB
__device__ float  g_agg2[NN * HID];      // 25.6 MB

// ---------------- 1) init ----------------
__global__ void k_init() {
    int i = blockIdx.x * 256 + threadIdx.x;
    if (i < NN) g_deg[i] = 1;
    if (i == 0) g_total = 0;
}

// ---------------- 2) degree histogram (2 edges/thread, RED no-return) ----------------
__global__ void k_deg(const int* __restrict__ ei) {
    int t = blockIdx.x * 256 + threadIdx.x;
    int2 d2 = reinterpret_cast<const int2*>(ei + ER)[t];
    atomicAdd(&g_deg[d2.x], 1);
    atomicAdd(&g_deg[d2.y], 1);
}

// ---------------- 3) dinv + CSR row allocation ----------------
__global__ void k_dinv_alloc() {
    int i    = blockIdx.x * 256 + threadIdx.x;
    int lane = threadIdx.x & 31;
    int cnt  = 0;
    if (i < NN) {
        int d = g_deg[i];
        g_dinv[i] = rsqrtf((float)d);
        cnt = d - 1;
    }
    int incl = cnt;
#pragma unroll
    for (int off = 1; off < 32; off <<= 1) {
        int t = __shfl_up_sync(0xffffffffu, incl, off);
        if (lane >= off) incl += t;
    }
    int total = __shfl_sync(0xffffffffu, incl, 31);
    int base  = 0;
    if (lane == 31) base = atomicAdd(&g_total, total);
    base = __shfl_sync(0xffffffffu, base, 31);
    if (i < NN) {
        int start = base + incl - cnt;
        g_rowstart[i] = start;
        g_cursor[i]   = start;
    }
}

// ---------------- 4) scatter edges (lean, 2 edges/thread) ----------------
__global__ void k_scatter(const int* __restrict__ ei) {
    int t = blockIdx.x * 256 + threadIdx.x;
    int2 s2 = reinterpret_cast<const int2*>(ei)[t];
    int2 d2 = reinterpret_cast<const int2*>(ei + ER)[t];
    int p0 = atomicAdd(&g_cursor[d2.x], 1);
    int p1 = atomicAdd(&g_cursor[d2.y], 1);
    g_col[p0] = s2.x;
    g_col[p1] = s2.y;
}

// ---------------- 5) aggregate embeddings (warp per node, MLP=4) ----------------
__global__ void __launch_bounds__(256) k_agg_emb(const float* __restrict__ emb) {
    int w    = (blockIdx.x * 256 + threadIdx.x) >> 5;
    int lane = threadIdx.x & 31;
    float di  = g_dinv[w];
    float acc = emb[w * EMB + lane] * (di * di);     // self loop
    int start = g_rowstart[w], cnt = g_deg[w] - 1, e = 0;
    for (; e + 4 <= cnt; e += 4) {
        int s0 = g_col[start + e];
        int s1 = g_col[start + e + 1];
        int s2 = g_col[start + e + 2];
        int s3 = g_col[start + e + 3];
        float r0 = emb[s0 * EMB + lane];
        float r1 = emb[s1 * EMB + lane];
        float r2 = emb[s2 * EMB + lane];
        float r3 = emb[s3 * EMB + lane];
        acc += r0 * (g_dinv[s0] * di);
        acc += r1 * (g_dinv[s1] * di);
        acc += r2 * (g_dinv[s2] * di);
        acc += r3 * (g_dinv[s3] * di);
    }
    for (; e < cnt; e++) {
        int s = g_col[start + e];
        acc += emb[s * EMB + lane] * (g_dinv[s] * di);
    }
    g_aggemb[w * EMB + lane] = acc;
}

// ---------------- 6) GEMM1: h1 = relu(aggemb @ W1 + b1) -> fp16, 64-row tiles ----------------
__global__ void __launch_bounds__(256) k_gemm1(const float* __restrict__ W1,
                                               const float* __restrict__ b1) {
    __shared__ float As[TILE * EMB];     // 8 KB
    int tid  = threadIdx.x;
    int tcol = (tid & 15) * 8;           // 0..120
    int trow = (tid >> 4) * 4;           // 0..60
    int row0 = blockIdx.x * TILE;
    u64 bias[4];
    bias[0] = packf2(__ldg(&b1[tcol]),     __ldg(&b1[tcol + 1]));
    bias[1] = packf2(__ldg(&b1[tcol + 2]), __ldg(&b1[tcol + 3]));
    bias[2] = packf2(__ldg(&b1[tcol + 4]), __ldg(&b1[tcol + 5]));
    bias[3] = packf2(__ldg(&b1[tcol + 6]), __ldg(&b1[tcol + 7]));

    // load 64x32 A tile (512 float4, 2 per thread)
#pragma unroll
    for (int i = 0; i < 2; i++) {
        int idx = tid + i * 256;                     // float4 index
        int gr  = row0 + (idx >> 3);
        reinterpret_cast<float4*>(As)[idx] = (gr < NN)
            ? reinterpret_cast<const float4*>(g_aggemb)[gr * 8 + (idx & 7)]
            : make_float4(0.f, 0.f, 0.f, 0.f);
    }
    __syncthreads();

    u64 acc[4][4];
#pragma unroll
    for (int r = 0; r < 4; r++)
#pragma unroll
        for (int c = 0; c < 4; c++) acc[r][c] = bias[c];
#pragma unroll
    for (int k = 0; k < EMB; k++) {
        ulonglong2 wa = __ldg(reinterpret_cast<const ulonglong2*>(&W1[k * HID + tcol]));
        ulonglong2 wb = __ldg(reinterpret_cast<const ulonglong2*>(&W1[k * HID + tcol + 4]));
#pragma unroll
        for (int r = 0; r < 4; r++) {
            u64 a = dup2(As[(trow + r) * EMB + k]);
            ffma2(acc[r][0], a, wa.x); ffma2(acc[r][1], a, wa.y);
            ffma2(acc[r][2], a, wb.x); ffma2(acc[r][3], a, wb.y);
        }
    }
#pragma unroll
    for (int r = 0; r < 4; r++) {
        int gr = row0 + trow + r;
        if (gr < NN) {
            float2 p0 = unpackf2(acc[r][0]);
            float2 p1 = unpackf2(acc[r][1]);
            float2 p2 = unpackf2(acc[r][2]);
            float2 p3 = unpackf2(acc[r][3]);
            __half2 h0 = __floats2half2_rn(fmaxf(p0.x, 0.f), fmaxf(p0.y, 0.f));
            __half2 h1 = __floats2half2_rn(fmaxf(p1.x, 0.f), fmaxf(p1.y, 0.f));
            __half2 h2 = __floats2half2_rn(fmaxf(p2.x, 0.f), fmaxf(p2.y, 0.f));
            __half2 h3 = __floats2half2_rn(fmaxf(p3.x, 0.f), fmaxf(p3.y, 0.f));
            uint4 st;
            st.x = *reinterpret_cast<unsigned*>(&h0);
            st.y = *reinterpret_cast<unsigned*>(&h1);
            st.z = *reinterpret_cast<unsigned*>(&h2);
            st.w = *reinterpret_cast<unsigned*>(&h3);
            *reinterpret_cast<uint4*>(&g_h1h[gr * HID + tcol]) = st;
        }
    }
}

// ---------------- 7) aggregate h1 (fp16 gather, fp32 accum, MLP=4) ----------------
__global__ void __launch_bounds__(256) k_agg_h1() {
    int w    = (blockIdx.x * 256 + threadIdx.x) >> 5;
    int lane = threadIdx.x & 31;
    float di = g_dinv[w];
    const uint2* hv = reinterpret_cast<const uint2*>(g_h1h);
    uint2 v = hv[w * 32 + lane];
    float2 vl = __half22float2(*reinterpret_cast<__half2*>(&v.x));
    float2 vh = __half22float2(*reinterpret_cast<__half2*>(&v.y));
    float sw = di * di;
    float4 acc = make_float4(vl.x * sw, vl.y * sw, vh.x * sw, vh.y * sw);
    int start = g_rowstart[w], cnt = g_deg[w] - 1, e = 0;
    for (; e + 4 <= cnt; e += 4) {
        int s0 = g_col[start + e];
        int s1 = g_col[start + e + 1];
        int s2 = g_col[start + e + 2];
        int s3 = g_col[start + e + 3];
        uint2 u0 = hv[s0 * 32 + lane];
        uint2 u1 = hv[s1 * 32 + lane];
        uint2 u2 = hv[s2 * 32 + lane];
        uint2 u3 = hv[s3 * 32 + lane];
        acc16(acc, u0, g_dinv[s0] * di);
        acc16(acc, u1, g_dinv[s1] * di);
        acc16(acc, u2, g_dinv[s2] * di);
        acc16(acc, u3, g_dinv[s3] * di);
    }
    for (; e < cnt; e++) {
        int s = g_col[start + e];
        uint2 u = hv[s * 32 + lane];
        acc16(acc, u, g_dinv[s] * di);
    }
    reinterpret_cast<float4*>(g_agg2)[w * 32 + lane] = acc;
}

// ---------------- 8) GEMM2: out = agg2 @ W2 + b2, 64-row tiles, 4x8 FFMA2 ----------------
__global__ void __launch_bounds__(256) k_gemm2(const float* __restrict__ W2,
                                               const float* __restrict__ b2,
                                               float* __restrict__ out) {
    __shared__ float As[TILE * HID];     // 32 KB
    int tid  = threadIdx.x;
    int tcol = (tid & 15) * 8;           // 0..120
    int trow = (tid >> 4) * 4;           // 0..60
    int row0 = blockIdx.x * TILE;
    u64 bias[4];
    bias[0] = packf2(__ldg(&b2[tcol]),     __ldg(&b2[tcol + 1]));
    bias[1] = packf2(__ldg(&b2[tcol + 2]), __ldg(&b2[tcol + 3]));
    bias[2] = packf2(__ldg(&b2[tcol + 4]), __ldg(&b2[tcol + 5]));
    bias[3] = packf2(__ldg(&b2[tcol + 6]), __ldg(&b2[tcol + 7]));

    // load 64x128 A tile (2048 float4, 8 per thread)
#pragma unroll
    for (int i = 0; i < 8; i++) {
        int idx = tid + i * 256;                     // float4 index
        int gr  = row0 + (idx >> 5);
        reinterpret_cast<float4*>(As)[idx] = (gr < NN)
            ? reinterpret_cast<const float4*>(g_agg2)[gr * 32 + (idx & 31)]
            : make_float4(0.f, 0.f, 0.f, 0.f);
    }
    __syncthreads();

    u64 acc[4][4];
#pragma unroll
    for (int r = 0; r < 4; r++)
#pragma unroll
        for (int c = 0; c < 4; c++) acc[r][c] = bias[c];
#pragma unroll 4
    for (int k = 0; k < HID; k++) {
        ulonglong2 wa = __ldg(reinterpret_cast<const ulonglong2*>(&W2[k * HID + tcol]));
        ulonglong2 wb = __ldg(reinterpret_cast<const ulonglong2*>(&W2[k * HID + tcol + 4]));
#pragma unroll
        for (int r = 0; r < 4; r++) {
            u64 a = dup2(As[(trow + r) * HID + k]);
            ffma2(acc[r][0], a, wa.x); ffma2(acc[r][1], a, wa.y);
            ffma2(acc[r][2], a, wb.x); ffma2(acc[r][3], a, wb.y);
        }
    }
#pragma unroll
    for (int r = 0; r < 4; r++) {
        int gr = row0 + trow + r;
        if (gr < NN) {
            float2 p0 = unpackf2(acc[r][0]);
            float2 p1 = unpackf2(acc[r][1]);
            float2 p2 = unpackf2(acc[r][2]);
            float2 p3 = unpackf2(acc[r][3]);
            *reinterpret_cast<float4*>(&out[gr * HID + tcol])     = make_float4(p0.x, p0.y, p1.x, p1.y);
            *reinterpret_cast<float4*>(&out[gr * HID + tcol + 4]) = make_float4(p2.x, p2.y, p3.x, p3.y);
        }
    }
}

// ---------------- host launcher ----------------
extern "C" void kernel_launch(void* const* d_in, const int* in_sizes, int n_in,
                              void* d_out, int out_size) {
    const int*   ei  = (const int*)d_in[1];
    const float* emb = (const float*)d_in[2];
    const float* W1  = (const float*)d_in[3];
    const float* b1  = (const float*)d_in[4];
    const float* W2  = (const float*)d_in[5];
    const float* b2  = (const float*)d_in[6];
    float* out = (float*)d_out;

    const int NT = (NN + TILE - 1) / TILE;           // 782
    k_init      <<<(NN + 255) / 256, 256>>>();
    k_deg       <<<ER / 2 / 256, 256>>>(ei);
    k_dinv_alloc<<<(NN + 255) / 256, 256>>>();
    k_scatter   <<<ER / 2 / 256, 256>>>(ei);
    k_agg_emb   <<<(NN * 32) / 256, 256>>>(emb);
    k_gemm1     <<<NT, 256>>>(W1, b1);
    k_agg_h1    <<<(NN * 32) / 256, 256>>>();
    k_gemm2     <<<NT, 256>>>(W2, b2, out);
}

// round 8
// speedup vs baseline: 1.1418x; 1.0098x over previous
#include <cuda_runtime.h>
#include <cuda_fp16.h>

#define NN   50000
#define ER   1600000
#define EMB  32
#define HID  128
#define TILE 64
#define CAP  128          // bucket capacity per node (E[deg]=32, P(>128)~1e-40)
#define OVMAX 8192

typedef unsigned long long u64;

// ---- packed f32x2 helpers (sm_103a FFMA2 path, PTX-only) ----
__device__ __forceinline__ u64 dup2(float a) {
    u64 r; asm("mov.b64 %0, {%1, %1};" : "=l"(r) : "f"(a)); return r;
}
__device__ __forceinline__ u64 packf2(float a, float b) {
    u64 r; asm("mov.b64 %0, {%1, %2};" : "=l"(r) : "f"(a), "f"(b)); return r;
}
__device__ __forceinline__ void ffma2(u64& d, u64 a, u64 b) {
    asm("fma.rn.f32x2 %0, %1, %2, %0;" : "+l"(d) : "l"(a), "l"(b));
}
__device__ __forceinline__ float2 unpackf2(u64 v) {
    float2 r; asm("mov.b64 {%0, %1}, %2;" : "=f"(r.x), "=f"(r.y) : "l"(v)); return r;
}

__device__ __forceinline__ void acc16(float4& acc, uint2 u, float wgt) {
    float2 ul = __half22float2(*reinterpret_cast<__half2*>(&u.x));
    float2 uh = __half22float2(*reinterpret_cast<__half2*>(&u.y));
    acc.x += ul.x * wgt; acc.y += ul.y * wgt;
    acc.z += uh.x * wgt; acc.w += uh.y * wgt;
}

// ---------------- device scratch (static, no cudaMalloc) ----------------
__device__ int    g_cursor[NN];
__device__ float  g_dinv[NN];
__device__ int    g_col[NN * CAP];       // 25.6 MB direct buckets
__device__ int    g_ovcnt;
__device__ int2   g_ov[OVMAX];
__device__ float  g_aggemb[NN * EMB];    //  6.4 MB
__device__ __half g_h1h[NN * HID];       // 12.8 MB
__device__ float  g_agg2[NN * HID];      // 25.6 MB

// ---------------- 1) init: zero cursors + overflow count ----------------
__global__ void k_init() {
    int i = blockIdx.x * 256 + threadIdx.x;
    if (i < NN) g_cursor[i] = 0;
    if (i == 0) g_ovcnt = 0;
}

// ---------------- 2) direct-bucket scatter (2 edges/thread) ----------------
__global__ void k_scatter(const int* __restrict__ ei) {
    int t = blockIdx.x * 256 + threadIdx.x;          // t < ER/2
    int2 s2 = reinterpret_cast<const int2*>(ei)[t];
    int2 d2 = reinterpret_cast<const int2*>(ei + ER)[t];
    int p0 = atomicAdd(&g_cursor[d2.x], 1);
    int p1 = atomicAdd(&g_cursor[d2.y], 1);
    if (p0 < CAP) g_col[d2.x * CAP + p0] = s2.x;
    else { int o = atomicAdd(&g_ovcnt, 1); if (o < OVMAX) g_ov[o] = make_int2(d2.x, s2.x); }
    if (p1 < CAP) g_col[d2.y * CAP + p1] = s2.y;
    else { int o = atomicAdd(&g_ovcnt, 1); if (o < OVMAX) g_ov[o] = make_int2(d2.y, s2.y); }
}

// ---------------- 3) dinv from final cursor counts ----------------
__global__ void k_dinv() {
    int i = blockIdx.x * 256 + threadIdx.x;
    if (i < NN) g_dinv[i] = rsqrtf((float)(g_cursor[i] + 1));   // +1 self loop
}

// ---------------- 4) aggregate embeddings (warp/node, coalesced col + shfl) ----------------
__global__ void __launch_bounds__(256) k_agg_emb(const float* __restrict__ emb) {
    int w    = (blockIdx.x * 256 + threadIdx.x) >> 5;
    int lane = threadIdx.x & 31;
    float di  = g_dinv[w];
    float acc = emb[w * EMB + lane] * (di * di);     // self loop
    int cnt = min(g_cursor[w], CAP);
    const int* cb = g_col + w * CAP;
    for (int base = 0; base < cnt; base += 32) {
        int c = cb[base + lane];                     // coalesced 128B (in-bounds; extras unused)
        int m = min(32, cnt - base);
        int j = 0;
        for (; j + 4 <= m; j += 4) {
            int s0 = __shfl_sync(0xffffffffu, c, j);
            int s1 = __shfl_sync(0xffffffffu, c, j + 1);
            int s2 = __shfl_sync(0xffffffffu, c, j + 2);
            int s3 = __shfl_sync(0xffffffffu, c, j + 3);
            float r0 = emb[s0 * EMB + lane];
            float r1 = emb[s1 * EMB + lane];
            float r2 = emb[s2 * EMB + lane];
            float r3 = emb[s3 * EMB + lane];
            acc += r0 * (g_dinv[s0] * di);
            acc += r1 * (g_dinv[s1] * di);
            acc += r2 * (g_dinv[s2] * di);
            acc += r3 * (g_dinv[s3] * di);
        }
        for (; j < m; j++) {
            int s = __shfl_sync(0xffffffffu, c, j);
            acc += emb[s * EMB + lane] * (g_dinv[s] * di);
        }
    }
    g_aggemb[w * EMB + lane] = acc;
}

// ---------------- 4b) overflow fallback for layer-1 agg (normally empty) ----------------
__global__ void k_ovf1(const float* __restrict__ emb) {
    int nov = min(g_ovcnt, OVMAX);
    int lane = threadIdx.x & 31;
    int warp = (blockIdx.x * 256 + threadIdx.x) >> 5;
    int nw   = (gridDim.x * 256) >> 5;
    for (int i = warp; i < nov; i += nw) {
        int2 e = g_ov[i];
        float wgt = g_dinv[e.y] * g_dinv[e.x];
        atomicAdd(&g_aggemb[e.x * EMB + lane], emb[e.y * EMB + lane] * wgt);
    }
}

// ---------------- 5) GEMM1: h1 = relu(aggemb @ W1 + b1) -> fp16 ----------------
__global__ void __launch_bounds__(256) k_gemm1(const float* __restrict__ W1,
                                               const float* __restrict__ b1) {
    __shared__ float As[TILE * EMB];     // 8 KB
    int tid  = threadIdx.x;
    int tcol = (tid & 15) * 8;
    int trow = (tid >> 4) * 4;
    int row0 = blockIdx.x * TILE;
    u64 bias[4];
    bias[0] = packf2(__ldg(&b1[tcol]),     __ldg(&b1[tcol + 1]));
    bias[1] = packf2(__ldg(&b1[tcol + 2]), __ldg(&b1[tcol + 3]));
    bias[2] = packf2(__ldg(&b1[tcol + 4]), __ldg(&b1[tcol + 5]));
    bias[3] = packf2(__ldg(&b1[tcol + 6]), __ldg(&b1[tcol + 7]));

#pragma unroll
    for (int i = 0; i < 2; i++) {
        int idx = tid + i * 256;
        int gr  = row0 + (idx >> 3);
        reinterpret_cast<float4*>(As)[idx] = (gr < NN)
            ? reinterpret_cast<const float4*>(g_aggemb)[gr * 8 + (idx & 7)]
            : make_float4(0.f, 0.f, 0.f, 0.f);
    }
    __syncthreads();

    u64 acc[4][4];
#pragma unroll
    for (int r = 0; r < 4; r++)
#pragma unroll
        for (int c = 0; c < 4; c++) acc[r][c] = bias[c];
#pragma unroll
    for (int k = 0; k < EMB; k++) {
        ulonglong2 wa = __ldg(reinterpret_cast<const ulonglong2*>(&W1[k * HID + tcol]));
        ulonglong2 wb = __ldg(reinterpret_cast<const ulonglong2*>(&W1[k * HID + tcol + 4]));
#pragma unroll
        for (int r = 0; r < 4; r++) {
            u64 a = dup2(As[(trow + r) * EMB + k]);
            ffma2(acc[r][0], a, wa.x); ffma2(acc[r][1], a, wa.y);
            ffma2(acc[r][2], a, wb.x); ffma2(acc[r][3], a, wb.y);
        }
    }
#pragma unroll
    for (int r = 0; r < 4; r++) {
        int gr = row0 + trow + r;
        if (gr < NN) {
            float2 p0 = unpackf2(acc[r][0]);
            float2 p1 = unpackf2(acc[r][1]);
            float2 p2 = unpackf2(acc[r][2]);
            float2 p3 = unpackf2(acc[r][3]);
            __half2 h0 = __floats2half2_rn(fmaxf(p0.x, 0.f), fmaxf(p0.y, 0.f));
            __half2 h1 = __floats2half2_rn(fmaxf(p1.x, 0.f), fmaxf(p1.y, 0.f));
            __half2 h2 = __floats2half2_rn(fmaxf(p2.x, 0.f), fmaxf(p2.y, 0.f));
            __half2 h3 = __floats2half2_rn(fmaxf(p3.x, 0.f), fmaxf(p3.y, 0.f));
            uint4 st;
            st.x = *reinterpret_cast<unsigned*>(&h0);
            st.y = *reinterpret_cast<unsigned*>(&h1);
            st.z = *reinterpret_cast<unsigned*>(&h2);
            st.w = *reinterpret_cast<unsigned*>(&h3);
            *reinterpret_cast<uint4*>(&g_h1h[gr * HID + tcol]) = st;
        }
    }
}

// ---------------- 6) aggregate h1 (fp16 gather, fp32 accum, shfl col) ----------------
__global__ void __launch_bounds__(256) k_agg_h1() {
    int w    = (blockIdx.x * 256 + threadIdx.x) >> 5;
    int lane = threadIdx.x & 31;
    float di = g_dinv[w];
    const uint2* hv = reinterpret_cast<const uint2*>(g_h1h);
    uint2 v = hv[w * 32 + lane];
    float2 vl = __half22float2(*reinterpret_cast<__half2*>(&v.x));
    float2 vh = __half22float2(*reinterpret_cast<__half2*>(&v.y));
    float sw = di * di;
    float4 acc = make_float4(vl.x * sw, vl.y * sw, vh.x * sw, vh.y * sw);
    int cnt = min(g_cursor[w], CAP);
    const int* cb = g_col + w * CAP;
    for (int base = 0; base < cnt; base += 32) {
        int c = cb[base + lane];
        int m = min(32, cnt - base);
        int j = 0;
        for (; j + 4 <= m; j += 4) {
            int s0 = __shfl_sync(0xffffffffu, c, j);
            int s1 = __shfl_sync(0xffffffffu, c, j + 1);
            int s2 = __shfl_sync(0xffffffffu, c, j + 2);
            int s3 = __shfl_sync(0xffffffffu, c, j + 3);
            uint2 u0 = hv[s0 * 32 + lane];
            uint2 u1 = hv[s1 * 32 + lane];
            uint2 u2 = hv[s2 * 32 + lane];
            uint2 u3 = hv[s3 * 32 + lane];
            acc16(acc, u0, g_dinv[s0] * di);
            acc16(acc, u1, g_dinv[s1] * di);
            acc16(acc, u2, g_dinv[s2] * di);
            acc16(acc, u3, g_dinv[s3] * di);
        }
        for (; j < m; j++) {
            int s = __shfl_sync(0xffffffffu, c, j);
            uint2 u = hv[s * 32 + lane];
            acc16(acc, u, g_dinv[s] * di);
        }
    }
    reinterpret_cast<float4*>(g_agg2)[w * 32 + lane] = acc;
}

// ---------------- 6b) overflow fallback for layer-2 agg (normally empty) ----------------
__global__ void k_ovf2() {
    int nov = min(g_ovcnt, OVMAX);
    int lane = threadIdx.x & 31;
    int warp = (blockIdx.x * 256 + threadIdx.x) >> 5;
    int nw   = (gridDim.x * 256) >> 5;
    const uint2* hv = reinterpret_cast<const uint2*>(g_h1h);
    for (int i = warp; i < nov; i += nw) {
        int2 e = g_ov[i];
        float wgt = g_dinv[e.y] * g_dinv[e.x];
        uint2 u = hv[e.y * 32 + lane];
        float2 ul = __half22float2(*reinterpret_cast<__half2*>(&u.x));
        float2 uh = __half22float2(*reinterpret_cast<__half2*>(&u.y));
        atomicAdd(&g_agg2[e.x * HID + lane * 4],     ul.x * wgt);
        atomicAdd(&g_agg2[e.x * HID + lane * 4 + 1], ul.y * wgt);
        atomicAdd(&g_agg2[e.x * HID + lane * 4 + 2], uh.x * wgt);
        atomicAdd(&g_agg2[e.x * HID + lane * 4 + 3], uh.y * wgt);
    }
}

// ---------------- 7) GEMM2: out = agg2 @ W2 + b2, 4x8 FFMA2 ----------------
__global__ void __launch_bounds__(256) k_gemm2(const float* __restrict__ W2,
                                               const float* __restrict__ b2,
                                               float* __restrict__ out) {
    __shared__ float As[TILE * HID];     // 32 KB
    int tid  = threadIdx.x;
    int tcol = (tid & 15) * 8;
    int trow = (tid >> 4) * 4;
    int row0 = blockIdx.x * TILE;
    u64 bias[4];
    bias[0] = packf2(__ldg(&b2[tcol]),     __ldg(&b2[tcol + 1]));
    bias[1] = packf2(__ldg(&b2[tcol + 2]), __ldg(&b2[tcol + 3]));
    bias[2] = packf2(__ldg(&b2[tcol + 4]), __ldg(&b2[tcol + 5]));
    bias[3] = packf2(__ldg(&b2[tcol + 6]), __ldg(&b2[tcol + 7]));

#pragma unroll
    for (int i = 0; i < 8; i++) {
        int idx = tid + i * 256;
        int gr  = row0 + (idx >> 5);
        reinterpret_cast<float4*>(As)[idx] = (gr < NN)
            ? reinterpret_cast<const float4*>(g_agg2)[gr * 32 + (idx & 31)]
            : make_float4(0.f, 0.f, 0.f, 0.f);
    }
    __syncthreads();

    u64 acc[4][4];
#pragma unroll
    for (int r = 0; r < 4; r++)
#pragma unroll
        for (int c = 0; c < 4; c++) acc[r][c] = bias[c];
#pragma unroll 4
    for (int k = 0; k < HID; k++) {
        ulonglong2 wa = __ldg(reinterpret_cast<const ulonglong2*>(&W2[k * HID + tcol]));
        ulonglong2 wb = __ldg(reinterpret_cast<const ulonglong2*>(&W2[k * HID + tcol + 4]));
#pragma unroll
        for (int r = 0; r < 4; r++) {
            u64 a = dup2(As[(trow + r) * HID + k]);
            ffma2(acc[r][0], a, wa.x); ffma2(acc[r][1], a, wa.y);
            ffma2(acc[r][2], a, wb.x); ffma2(acc[r][3], a, wb.y);
        }
    }
#pragma unroll
    for (int r = 0; r < 4; r++) {
        int gr = row0 + trow + r;
        if (gr < NN) {
            float2 p0 = unpackf2(acc[r][0]);
            float2 p1 = unpackf2(acc[r][1]);
            float2 p2 = unpackf2(acc[r][2]);
            float2 p3 = unpackf2(acc[r][3]);
            *reinterpret_cast<float4*>(&out[gr * HID + tcol])     = make_float4(p0.x, p0.y, p1.x, p1.y);
            *reinterpret_cast<float4*>(&out[gr * HID + tcol + 4]) = make_float4(p2.x, p2.y, p3.x, p3.y);
        }
    }
}

// ---------------- host launcher ----------------
extern "C" void kernel_launch(void* const* d_in, const int* in_sizes, int n_in,
                              void* d_out, int out_size) {
    const int*   ei  = (const int*)d_in[1];
    const float* emb = (const float*)d_in[2];
    const float* W1  = (const float*)d_in[3];
    const float* b1  = (const float*)d_in[4];
    const float* W2  = (const float*)d_in[5];
    const float* b2  = (const float*)d_in[6];
    float* out = (float*)d_out;

    const int NT = (NN + TILE - 1) / TILE;           // 782
    k_init    <<<(NN + 255) / 256, 256>>>();
    k_scatter <<<ER / 2 / 256, 256>>>(ei);
    k_dinv    <<<(NN + 255) / 256, 256>>>();
    k_agg_emb <<<(NN * 32) / 256, 256>>>(emb);
    k_ovf1    <<<2, 256>>>(emb);
    k_gemm1   <<<NT, 256>>>(W1, b1);
    k_agg_h1  <<<(NN * 32) / 256, 256>>>();
    k_ovf2    <<<2, 256>>>();
    k_gemm2   <<<NT, 256>>>(W2, b2, out);
}

// round 11
// speedup vs baseline: 1.2153x; 1.0643x over previous
#include <cuda_runtime.h>
#include <cuda_fp16.h>

#define NN   50000
#define ER   1600000
#define EMB  32
#define HID  128
#define TILE 64
#define CAP  128          // bucket capacity per node (E[deg]=32, P(>128)~1e-40)
#define OVMAX 8192
#define FULL 0xffffffffu

typedef unsigned long long u64;

// ---- packed f32x2 helpers (sm_103a FFMA2 path, PTX-only) ----
__device__ __forceinline__ u64 dup2(float a) {
    u64 r; asm("mov.b64 %0, {%1, %1};" : "=l"(r) : "f"(a)); return r;
}
__device__ __forceinline__ u64 packf2(float a, float b) {
    u64 r; asm("mov.b64 %0, {%1, %2};" : "=l"(r) : "f"(a), "f"(b)); return r;
}
__device__ __forceinline__ void ffma2(u64& d, u64 a, u64 b) {
    asm("fma.rn.f32x2 %0, %1, %2, %0;" : "+l"(d) : "l"(a), "l"(b));
}
__device__ __forceinline__ float2 unpackf2(u64 v) {
    float2 r; asm("mov.b64 {%0, %1}, %2;" : "=f"(r.x), "=f"(r.y) : "l"(v)); return r;
}

// ---------------- device scratch (static, no cudaMalloc; 16B-aligned for LDG.128) ----------------
__device__ int    g_cursor[NN];
__device__ float  g_dinv[NN];
__device__ __align__(16) int    g_col[NN * CAP];     // 25.6 MB direct buckets
__device__ int    g_ovcnt;
__device__ int2   g_ov[OVMAX];
__device__ __align__(16) float  g_aggemb[NN * EMB];  //  6.4 MB
__device__ __align__(16) __half g_h1h[NN * HID];     // 12.8 MB
__device__ __align__(16) float  g_agg2[NN * HID];    // 25.6 MB

// ---------------- 1) init ----------------
__global__ void k_init() {
    int i = blockIdx.x * 256 + threadIdx.x;
    if (i < NN) g_cursor[i] = 0;
    if (i == 0) g_ovcnt = 0;
}

// ---------------- 2) direct-bucket scatter (2 edges/thread) ----------------
__global__ void k_scatter(const int* __restrict__ ei) {
    int t = blockIdx.x * 256 + threadIdx.x;          // t < ER/2
    int2 s2 = reinterpret_cast<const int2*>(ei)[t];
    int2 d2 = reinterpret_cast<const int2*>(ei + ER)[t];
    int p0 = atomicAdd(&g_cursor[d2.x], 1);
    int p1 = atomicAdd(&g_cursor[d2.y], 1);
    if (p0 < CAP) g_col[d2.x * CAP + p0] = s2.x;
    else { int o = atomicAdd(&g_ovcnt, 1); if (o < OVMAX) g_ov[o] = make_int2(d2.x, s2.x); }
    if (p1 < CAP) g_col[d2.y * CAP + p1] = s2.y;
    else { int o = atomicAdd(&g_ovcnt, 1); if (o < OVMAX) g_ov[o] = make_int2(d2.y, s2.y); }
}

// ---------------- 3) dinv from final cursor counts ----------------
__global__ void k_dinv() {
    int i = blockIdx.x * 256 + threadIdx.x;
    if (i < NN) g_dinv[i] = rsqrtf((float)(g_cursor[i] + 1));   // +1 self loop
}

// ---------------- 4) aggregate embeddings: warp/node, 4 edges in flight ----------------
// lane = 8*g + l : group g handles edge jb+g; sublane l owns dims [4l, 4l+4).
// Inner loop bound m is warp-uniform -> all lanes execute every __shfl_sync.
__global__ void __launch_bounds__(256) k_agg_emb(const float* __restrict__ emb) {
    int w    = (blockIdx.x * 256 + threadIdx.x) >> 5;
    int lane = threadIdx.x & 31;
    int g    = lane >> 3;
    int l    = lane & 7;
    float di = g_dinv[w];
    float4 acc = make_float4(0.f, 0.f, 0.f, 0.f);
    int cnt = min(g_cursor[w], CAP);
    const int* cb = g_col + w * CAP;
    for (int base = 0; base < cnt; base += 32) {
        int c = cb[base + lane];                     // coalesced 128B
        int m = min(32, cnt - base);                 // warp-uniform
        for (int jb = 0; jb < m; jb += 4) {          // uniform trip count
            int  j   = jb + g;
            bool act = (j < m);
            int  s   = __shfl_sync(FULL, c, act ? j : 0);
            if (act) {
                float ns = g_dinv[s] * di;
                float4 r = *reinterpret_cast<const float4*>(&emb[s * EMB + l * 4]);
                acc.x += r.x * ns; acc.y += r.y * ns;
                acc.z += r.z * ns; acc.w += r.w * ns;
            }
        }
    }
    // reduce across the 4 groups (lanes differing in bits 3,4)
#pragma unroll
    for (int off = 8; off <= 16; off <<= 1) {
        acc.x += __shfl_xor_sync(FULL, acc.x, off);
        acc.y += __shfl_xor_sync(FULL, acc.y, off);
        acc.z += __shfl_xor_sync(FULL, acc.z, off);
        acc.w += __shfl_xor_sync(FULL, acc.w, off);
    }
    if (g == 0) {
        float4 v = *reinterpret_cast<const float4*>(&emb[w * EMB + l * 4]);
        float sw = di * di;                          // self loop
        acc.x += v.x * sw; acc.y += v.y * sw;
        acc.z += v.z * sw; acc.w += v.w * sw;
        *reinterpret_cast<float4*>(&g_aggemb[w * EMB + l * 4]) = acc;
    }
}

// ---------------- 4b) overflow fallback for layer-1 agg (normally empty) ----------------
__global__ void k_ovf1(const float* __restrict__ emb) {
    int nov = min(g_ovcnt, OVMAX);
    int lane = threadIdx.x & 31;
    int warp = (blockIdx.x * 256 + threadIdx.x) >> 5;
    int nw   = (gridDim.x * 256) >> 5;
    for (int i = warp; i < nov; i += nw) {
        int2 e = g_ov[i];
        float wgt = g_dinv[e.y] * g_dinv[e.x];
        atomicAdd(&g_aggemb[e.x * EMB + lane], emb[e.y * EMB + lane] * wgt);
    }
}

// ---------------- 5) GEMM1: h1 = relu(aggemb @ W1 + b1) -> fp16 ----------------
__global__ void __launch_bounds__(256) k_gemm1(const float* __restrict__ W1,
                                               const float* __restrict__ b1) {
    __shared__ float As[TILE * EMB];     // 8 KB
    int tid  = threadIdx.x;
    int tcol = (tid & 15) * 8;
    int trow = (tid >> 4) * 4;
    int row0 = blockIdx.x * TILE;
    u64 bias[4];
    bias[0] = packf2(__ldg(&b1[tcol]),     __ldg(&b1[tcol + 1]));
    bias[1] = packf2(__ldg(&b1[tcol + 2]), __ldg(&b1[tcol + 3]));
    bias[2] = packf2(__ldg(&b1[tcol + 4]), __ldg(&b1[tcol + 5]));
    bias[3] = packf2(__ldg(&b1[tcol + 6]), __ldg(&b1[tcol + 7]));

#pragma unroll
    for (int i = 0; i < 2; i++) {
        int idx = tid + i * 256;
        int gr  = row0 + (idx >> 3);
        reinterpret_cast<float4*>(As)[idx] = (gr < NN)
            ? reinterpret_cast<const float4*>(g_aggemb)[gr * 8 + (idx & 7)]
            : make_float4(0.f, 0.f, 0.f, 0.f);
    }
    __syncthreads();

    u64 acc[4][4];
#pragma unroll
    for (int r = 0; r < 4; r++)
#pragma unroll
        for (int c = 0; c < 4; c++) acc[r][c] = bias[c];
#pragma unroll
    for (int k = 0; k < EMB; k++) {
        ulonglong2 wa = __ldg(reinterpret_cast<const ulonglong2*>(&W1[k * HID + tcol]));
        ulonglong2 wb = __ldg(reinterpret_cast<const ulonglong2*>(&W1[k * HID + tcol + 4]));
#pragma unroll
        for (int r = 0; r < 4; r++) {
            u64 a = dup2(As[(trow + r) * EMB + k]);
            ffma2(acc[r][0], a, wa.x); ffma2(acc[r][1], a, wa.y);
            ffma2(acc[r][2], a, wb.x); ffma2(acc[r][3], a, wb.y);
        }
    }
#pragma unroll
    for (int r = 0; r < 4; r++) {
        int gr = row0 + trow + r;
        if (gr < NN) {
            float2 p0 = unpackf2(acc[r][0]);
            float2 p1 = unpackf2(acc[r][1]);
            float2 p2 = unpackf2(acc[r][2]);
            float2 p3 = unpackf2(acc[r][3]);
            __half2 h0 = __floats2half2_rn(fmaxf(p0.x, 0.f), fmaxf(p0.y, 0.f));
            __half2 h1 = __floats2half2_rn(fmaxf(p1.x, 0.f), fmaxf(p1.y, 0.f));
            __half2 h2 = __floats2half2_rn(fmaxf(p2.x, 0.f), fmaxf(p2.y, 0.f));
            __half2 h3 = __floats2half2_rn(fmaxf(p3.x, 0.f), fmaxf(p3.y, 0.f));
            uint4 st;
            st.x = *reinterpret_cast<unsigned*>(&h0);
            st.y = *reinterpret_cast<unsigned*>(&h1);
            st.z = *reinterpret_cast<unsigned*>(&h2);
            st.w = *reinterpret_cast<unsigned*>(&h3);
            *reinterpret_cast<uint4*>(&g_h1h[gr * HID + tcol]) = st;
        }
    }
}

// ---------------- 6) aggregate h1: warp/node, 2 edges in flight, uint4 fp16 ----------------
// lane = 16*g + l : group g handles edge jb+g; sublane l owns dims [8l, 8l+8).
__global__ void __launch_bounds__(256) k_agg_h1() {
    int w    = (blockIdx.x * 256 + threadIdx.x) >> 5;
    int lane = threadIdx.x & 31;
    int g    = lane >> 4;
    int l    = lane & 15;
    float di = g_dinv[w];
    float a0 = 0.f, a1 = 0.f, a2 = 0.f, a3 = 0.f,
          a4 = 0.f, a5 = 0.f, a6 = 0.f, a7 = 0.f;
    int cnt = min(g_cursor[w], CAP);
    const int* cb = g_col + w * CAP;
    const uint4* hv = reinterpret_cast<const uint4*>(g_h1h);   // 8 halves / uint4
    for (int base = 0; base < cnt; base += 32) {
        int c = cb[base + lane];
        int m = min(32, cnt - base);                 // warp-uniform
        for (int jb = 0; jb < m; jb += 2) {          // uniform trip count
            int  j   = jb + g;
            bool act = (j < m);
            int  s   = __shfl_sync(FULL, c, act ? j : 0);
            if (act) {
                float ns = g_dinv[s] * di;
                uint4 u  = hv[s * 16 + l];
                float2 f0 = __half22float2(*reinterpret_cast<__half2*>(&u.x));
                float2 f1 = __half22float2(*reinterpret_cast<__half2*>(&u.y));
                float2 f2 = __half22float2(*reinterpret_cast<__half2*>(&u.z));
                float2 f3 = __half22float2(*reinterpret_cast<__half2*>(&u.w));
                a0 += f0.x * ns; a1 += f0.y * ns;
                a2 += f1.x * ns; a3 += f1.y * ns;
                a4 += f2.x * ns; a5 += f2.y * ns;
                a6 += f3.x * ns; a7 += f3.y * ns;
            }
        }
    }
    // reduce across the 2 groups
    a0 += __shfl_xor_sync(FULL, a0, 16);
    a1 += __shfl_xor_sync(FULL, a1, 16);
    a2 += __shfl_xor_sync(FULL, a2, 16);
    a3 += __shfl_xor_sync(FULL, a3, 16);
    a4 += __shfl_xor_sync(FULL, a4, 16);
    a5 += __shfl_xor_sync(FULL, a5, 16);
    a6 += __shfl_xor_sync(FULL, a6, 16);
    a7 += __shfl_xor_sync(FULL, a7, 16);
    if (g == 0) {
        uint4 u = hv[w * 16 + l];                    // self loop
        float sw = di * di;
        float2 f0 = __half22float2(*reinterpret_cast<__half2*>(&u.x));
        float2 f1 = __half22float2(*reinterpret_cast<__half2*>(&u.y));
        float2 f2 = __half22float2(*reinterpret_cast<__half2*>(&u.z));
        float2 f3 = __half22float2(*reinterpret_cast<__half2*>(&u.w));
        a0 += f0.x * sw; a1 += f0.y * sw;
        a2 += f1.x * sw; a3 += f1.y * sw;
        a4 += f2.x * sw; a5 += f2.y * sw;
        a6 += f3.x * sw; a7 += f3.y * sw;
        float4* dst = reinterpret_cast<float4*>(&g_agg2[w * HID + l * 8]);
        dst[0] = make_float4(a0, a1, a2, a3);
        dst[1] = make_float4(a4, a5, a6, a7);
    }
}

// ---------------- 6b) overflow fallback for layer-2 agg (normally empty) ----------------
__global__ void k_ovf2() {
    int nov = min(g_ovcnt, OVMAX);
    int lane = threadIdx.x & 31;
    int warp = (blockIdx.x * 256 + threadIdx.x) >> 5;
    int nw   = (gridDim.x * 256) >> 5;
    const uint2* hv = reinterpret_cast<const uint2*>(g_h1h);
    for (int i = warp; i < nov; i += nw) {
        int2 e = g_ov[i];
        float wgt = g_dinv[e.y] * g_dinv[e.x];
        uint2 u = hv[e.y * 32 + lane];
        float2 ul = __half22float2(*reinterpret_cast<__half2*>(&u.x));
        float2 uh = __half22float2(*reinterpret_cast<__half2*>(&u.y));
        atomicAdd(&g_agg2[e.x * HID + lane * 4],     ul.x * wgt);
        atomicAdd(&g_agg2[e.x * HID + lane * 4 + 1], ul.y * wgt);
        atomicAdd(&g_agg2[e.x * HID + lane * 4 + 2], uh.x * wgt);
        atomicAdd(&g_agg2[e.x * HID + lane * 4 + 3], uh.y * wgt);
    }
}

// ---------------- 7) GEMM2: out = agg2 @ W2 + b2, 4x8 FFMA2 ----------------
__global__ void __launch_bounds__(256) k_gemm2(const float* __restrict__ W2,
                                               const float* __restrict__ b2,
                                               float* __restrict__ out) {
    __shared__ float As[TILE * HID];     // 32 KB
    int tid  = threadIdx.x;
    int tcol = (tid & 15) * 8;
    int trow = (tid >> 4) * 4;
    int row0 = blockIdx.x * TILE;
    u64 bias[4];
    bias[0] = packf2(__ldg(&b2[tcol]),     __ldg(&b2[tcol + 1]));
    bias[1] = packf2(__ldg(&b2[tcol + 2]), __ldg(&b2[tcol + 3]));
    bias[2] = packf2(__ldg(&b2[tcol + 4]), __ldg(&b2[tcol + 5]));
    bias[3] = packf2(__ldg(&b2[tcol + 6]), __ldg(&b2[tcol + 7]));

#pragma unroll
    for (int i = 0; i < 8; i++) {
        int idx = tid + i * 256;
        int gr  = row0 + (idx >> 5);
        reinterpret_cast<float4*>(As)[idx] = (gr < NN)
            ? reinterpret_cast<const float4*>(g_agg2)[gr * 32 + (idx & 31)]
            : make_float4(0.f, 0.f, 0.f, 0.f);
    }
    __syncthreads();

    u64 acc[4][4];
#pragma unroll
    for (int r = 0; r < 4; r++)
#pragma unroll
        for (int c = 0; c < 4; c++) acc[r][c] = bias[c];
#pragma unroll 4
    for (int k = 0; k < HID; k++) {
        ulonglong2 wa = __ldg(reinterpret_cast<const ulonglong2*>(&W2[k * HID + tcol]));
        ulonglong2 wb = __ldg(reinterpret_cast<const ulonglong2*>(&W2[k * HID + tcol + 4]));
#pragma unroll
        for (int r = 0; r < 4; r++) {
            u64 a = dup2(As[(trow + r) * HID + k]);
            ffma2(acc[r][0], a, wa.x); ffma2(acc[r][1], a, wa.y);
            ffma2(acc[r][2], a, wb.x); ffma2(acc[r][3], a, wb.y);
        }
    }
#pragma unroll
    for (int r = 0; r < 4; r++) {
        int gr = row0 + trow + r;
        if (gr < NN) {
            float2 p0 = unpackf2(acc[r][0]);
            float2 p1 = unpackf2(acc[r][1]);
            float2 p2 = unpackf2(acc[r][2]);
            float2 p3 = unpackf2(acc[r][3]);
            *reinterpret_cast<float4*>(&out[gr * HID + tcol])     = make_float4(p0.x, p0.y, p1.x, p1.y);
            *reinterpret_cast<float4*>(&out[gr * HID + tcol + 4]) = make_float4(p2.x, p2.y, p3.x, p3.y);
        }
    }
}

// ---------------- host launcher ----------------
extern "C" void kernel_launch(void* const* d_in, const int* in_sizes, int n_in,
                              void* d_out, int out_size) {
    const int*   ei  = (const int*)d_in[1];
    const float* emb = (const float*)d_in[2];
    const float* W1  = (const float*)d_in[3];
    const float* b1  = (const float*)d_in[4];
    const float* W2  = (const float*)d_in[5];
    const float* b2  = (const float*)d_in[6];
    float* out = (float*)d_out;

    const int NT = (NN + TILE - 1) / TILE;           // 782
    k_init    <<<(NN + 255) / 256, 256>>>();
    k_scatter <<<ER / 2 / 256, 256>>>(ei);
    k_dinv    <<<(NN + 255) / 256, 256>>>();
    k_agg_emb <<<(NN * 32) / 256, 256>>>(emb);
    k_ovf1    <<<2, 256>>>(emb);
    k_gemm1   <<<NT, 256>>>(W1, b1);
    k_agg_h1  <<<(NN * 32) / 256, 256>>>();
    k_ovf2    <<<2, 256>>>();
    k_gemm2   <<<NT, 256>>>(W2, b2, out);
}

// round 12
// speedup vs baseline: 1.2236x; 1.0069x over previous
#include <cuda_runtime.h>
#include <cuda_fp16.h>

#define NN   50000
#define ER   1600000
#define EMB  32
#define HID  128
#define TILE 64
#define CAP  128          // bucket capacity per node (E[deg]=32, P(>128)~1e-40)
#define OVMAX 8192
#define FULL 0xffffffffu

typedef unsigned long long u64;

// ---- packed f32x2 helpers (sm_103a FFMA2 path, PTX-only) ----
__device__ __forceinline__ u64 dup2(float a) {
    u64 r; asm("mov.b64 %0, {%1, %1};" : "=l"(r) : "f"(a)); return r;
}
__device__ __forceinline__ u64 packf2(float a, float b) {
    u64 r; asm("mov.b64 %0, {%1, %2};" : "=l"(r) : "f"(a), "f"(b)); return r;
}
__device__ __forceinline__ void ffma2(u64& d, u64 a, u64 b) {
    asm("fma.rn.f32x2 %0, %1, %2, %0;" : "+l"(d) : "l"(a), "l"(b));
}
__device__ __forceinline__ float2 unpackf2(u64 v) {
    float2 r; asm("mov.b64 {%0, %1}, %2;" : "=f"(r.x), "=f"(r.y) : "l"(v)); return r;
}

// ---------------- device scratch (static, no cudaMalloc; 16B-aligned for LDG.128) ----------------
__device__ int    g_cursor[NN];
__device__ float  g_dinv[NN];
__device__ __align__(16) int    g_col[NN * CAP];     // 25.6 MB direct buckets
__device__ int    g_ovcnt;
__device__ int2   g_ov[OVMAX];
__device__ __align__(16) float  g_aggemb[NN * EMB];  //  6.4 MB
__device__ __align__(16) __half g_h1h[NN * HID];     // 12.8 MB
__device__ __align__(16) float  g_agg2[NN * HID];    // 25.6 MB

// ---------------- 1) init ----------------
__global__ void k_init() {
    int i = blockIdx.x * 256 + threadIdx.x;
    if (i < NN) g_cursor[i] = 0;
    if (i == 0) g_ovcnt = 0;
}

// ---------------- 2) direct-bucket scatter (4 edges/thread, MLP=4) ----------------
__global__ void k_scatter(const int* __restrict__ ei) {
    int t = blockIdx.x * 256 + threadIdx.x;          // t < ER/4
    if (t >= ER / 4) return;
    int4 s4 = reinterpret_cast<const int4*>(ei)[t];
    int4 d4 = reinterpret_cast<const int4*>(ei + ER)[t];
    int p0 = atomicAdd(&g_cursor[d4.x], 1);
    int p1 = atomicAdd(&g_cursor[d4.y], 1);
    int p2 = atomicAdd(&g_cursor[d4.z], 1);
    int p3 = atomicAdd(&g_cursor[d4.w], 1);
    if (p0 < CAP) g_col[d4.x * CAP + p0] = s4.x;
    else { int o = atomicAdd(&g_ovcnt, 1); if (o < OVMAX) g_ov[o] = make_int2(d4.x, s4.x); }
    if (p1 < CAP) g_col[d4.y * CAP + p1] = s4.y;
    else { int o = atomicAdd(&g_ovcnt, 1); if (o < OVMAX) g_ov[o] = make_int2(d4.y, s4.y); }
    if (p2 < CAP) g_col[d4.z * CAP + p2] = s4.z;
    else { int o = atomicAdd(&g_ovcnt, 1); if (o < OVMAX) g_ov[o] = make_int2(d4.z, s4.z); }
    if (p3 < CAP) g_col[d4.w * CAP + p3] = s4.w;
    else { int o = atomicAdd(&g_ovcnt, 1); if (o < OVMAX) g_ov[o] = make_int2(d4.w, s4.w); }
}

// ---------------- 3) dinv from final cursor counts ----------------
__global__ void k_dinv() {
    int i = blockIdx.x * 256 + threadIdx.x;
    if (i < NN) g_dinv[i] = rsqrtf((float)(g_cursor[i] + 1));   // +1 self loop
}

// ---------------- 4) aggregate embeddings: warp/node, 4 edges in flight ----------------
// lane = 8*g + l : group g handles edge jb+g; sublane l owns dims [4l, 4l+4).
// Fast path (m==32): fully unrolled, unpredicated. Tail: branch-free select-zero.
__global__ void __launch_bounds__(256) k_agg_emb(const float* __restrict__ emb) {
    int w    = (blockIdx.x * 256 + threadIdx.x) >> 5;
    int lane = threadIdx.x & 31;
    int g    = lane >> 3;
    int l    = lane & 7;
    float di = g_dinv[w];
    float4 acc = make_float4(0.f, 0.f, 0.f, 0.f);
    int cnt = min(g_cursor[w], CAP);
    const int* cb = g_col + w * CAP;
    for (int base = 0; base < cnt; base += 32) {
        int c = cb[base + lane];                     // coalesced 128B
        int m = min(32, cnt - base);                 // warp-uniform
        if (m == 32) {
#pragma unroll
            for (int jb = 0; jb < 32; jb += 4) {
                int   s  = __shfl_sync(FULL, c, jb + g);
                float ns = g_dinv[s] * di;
                float4 r = *reinterpret_cast<const float4*>(&emb[s * EMB + l * 4]);
                acc.x += r.x * ns; acc.y += r.y * ns;
                acc.z += r.z * ns; acc.w += r.w * ns;
            }
        } else {
            for (int jb = 0; jb < m; jb += 4) {
                int  j   = jb + g;
                bool act = (j < m);
                int  s   = __shfl_sync(FULL, c, act ? j : 0);   // s always valid
                float ns = act ? g_dinv[s] * di : 0.f;
                float4 r = *reinterpret_cast<const float4*>(&emb[s * EMB + l * 4]);
                acc.x += r.x * ns; acc.y += r.y * ns;
                acc.z += r.z * ns; acc.w += r.w * ns;
            }
        }
    }
    // reduce across the 4 groups (lanes differing in bits 3,4)
#pragma unroll
    for (int off = 8; off <= 16; off <<= 1) {
        acc.x += __shfl_xor_sync(FULL, acc.x, off);
        acc.y += __shfl_xor_sync(FULL, acc.y, off);
        acc.z += __shfl_xor_sync(FULL, acc.z, off);
        acc.w += __shfl_xor_sync(FULL, acc.w, off);
    }
    if (g == 0) {
        float4 v = *reinterpret_cast<const float4*>(&emb[w * EMB + l * 4]);
        float sw = di * di;                          // self loop
        acc.x += v.x * sw; acc.y += v.y * sw;
        acc.z += v.z * sw; acc.w += v.w * sw;
        *reinterpret_cast<float4*>(&g_aggemb[w * EMB + l * 4]) = acc;
    }
}

// ---------------- 4b) overflow fallback for layer-1 agg (normally empty) ----------------
__global__ void k_ovf1(const float* __restrict__ emb) {
    int nov = min(g_ovcnt, OVMAX);
    int lane = threadIdx.x & 31;
    int warp = (blockIdx.x * 256 + threadIdx.x) >> 5;
    int nw   = (gridDim.x * 256) >> 5;
    for (int i = warp; i < nov; i += nw) {
        int2 e = g_ov[i];
        float wgt = g_dinv[e.y] * g_dinv[e.x];
        atomicAdd(&g_aggemb[e.x * EMB + lane], emb[e.y * EMB + lane] * wgt);
    }
}

// ---------------- 5) GEMM1: h1 = relu(aggemb @ W1 + b1) -> fp16 ----------------
__global__ void __launch_bounds__(256) k_gemm1(const float* __restrict__ W1,
                                               const float* __restrict__ b1) {
    __shared__ float As[TILE * EMB];     // 8 KB
    int tid  = threadIdx.x;
    int tcol = (tid & 15) * 8;
    int trow = (tid >> 4) * 4;
    int row0 = blockIdx.x * TILE;
    u64 bias[4];
    bias[0] = packf2(__ldg(&b1[tcol]),     __ldg(&b1[tcol + 1]));
    bias[1] = packf2(__ldg(&b1[tcol + 2]), __ldg(&b1[tcol + 3]));
    bias[2] = packf2(__ldg(&b1[tcol + 4]), __ldg(&b1[tcol + 5]));
    bias[3] = packf2(__ldg(&b1[tcol + 6]), __ldg(&b1[tcol + 7]));

#pragma unroll
    for (int i = 0; i < 2; i++) {
        int idx = tid + i * 256;
        int gr  = row0 + (idx >> 3);
        reinterpret_cast<float4*>(As)[idx] = (gr < NN)
            ? reinterpret_cast<const float4*>(g_aggemb)[gr * 8 + (idx & 7)]
            : make_float4(0.f, 0.f, 0.f, 0.f);
    }
    __syncthreads();

    u64 acc[4][4];
#pragma unroll
    for (int r = 0; r < 4; r++)
#pragma unroll
        for (int c = 0; c < 4; c++) acc[r][c] = bias[c];
#pragma unroll
    for (int k = 0; k < EMB; k++) {
        ulonglong2 wa = __ldg(reinterpret_cast<const ulonglong2*>(&W1[k * HID + tcol]));
        ulonglong2 wb = __ldg(reinterpret_cast<const ulonglong2*>(&W1[k * HID + tcol + 4]));
#pragma unroll
        for (int r = 0; r < 4; r++) {
            u64 a = dup2(As[(trow + r) * EMB + k]);
            ffma2(acc[r][0], a, wa.x); ffma2(acc[r][1], a, wa.y);
            ffma2(acc[r][2], a, wb.x); ffma2(acc[r][3], a, wb.y);
        }
    }
#pragma unroll
    for (int r = 0; r < 4; r++) {
        int gr = row0 + trow + r;
        if (gr < NN) {
            float2 p0 = unpackf2(acc[r][0]);
            float2 p1 = unpackf2(acc[r][1]);
            float2 p2 = unpackf2(acc[r][2]);
            float2 p3 = unpackf2(acc[r][3]);
            __half2 h0 = __floats2half2_rn(fmaxf(p0.x, 0.f), fmaxf(p0.y, 0.f));
            __half2 h1 = __floats2half2_rn(fmaxf(p1.x, 0.f), fmaxf(p1.y, 0.f));
            __half2 h2 = __floats2half2_rn(fmaxf(p2.x, 0.f), fmaxf(p2.y, 0.f));
            __half2 h3 = __floats2half2_rn(fmaxf(p3.x, 0.f), fmaxf(p3.y, 0.f));
            uint4 st;
            st.x = *reinterpret_cast<unsigned*>(&h0);
            st.y = *reinterpret_cast<unsigned*>(&h1);
            st.z = *reinterpret_cast<unsigned*>(&h2);
            st.w = *reinterpret_cast<unsigned*>(&h3);
            *reinterpret_cast<uint4*>(&g_h1h[gr * HID + tcol]) = st;
        }
    }
}

// ---------------- 6) aggregate h1: warp/node, 2 edges in flight, uint4 fp16 ----------------
// lane = 16*g + l : group g handles edge jb+g; sublane l owns dims [8l, 8l+8).
__global__ void __launch_bounds__(256) k_agg_h1() {
    int w    = (blockIdx.x * 256 + threadIdx.x) >> 5;
    int lane = threadIdx.x & 31;
    int g    = lane >> 4;
    int l    = lane & 15;
    float di = g_dinv[w];
    float a0 = 0.f, a1 = 0.f, a2 = 0.f, a3 = 0.f,
          a4 = 0.f, a5 = 0.f, a6 = 0.f, a7 = 0.f;
    int cnt = min(g_cursor[w], CAP);
    const int* cb = g_col + w * CAP;
    const uint4* hv = reinterpret_cast<const uint4*>(g_h1h);   // 8 halves / uint4
    for (int base = 0; base < cnt; base += 32) {
        int c = cb[base + lane];
        int m = min(32, cnt - base);                 // warp-uniform
        if (m == 32) {
#pragma unroll 4
            for (int jb = 0; jb < 32; jb += 2) {
                int   s  = __shfl_sync(FULL, c, jb + g);
                float ns = g_dinv[s] * di;
                uint4 u  = hv[s * 16 + l];
                float2 f0 = __half22float2(*reinterpret_cast<__half2*>(&u.x));
                float2 f1 = __half22float2(*reinterpret_cast<__half2*>(&u.y));
                float2 f2 = __half22float2(*reinterpret_cast<__half2*>(&u.z));
                float2 f3 = __half22float2(*reinterpret_cast<__half2*>(&u.w));
                a0 += f0.x * ns; a1 += f0.y * ns;
                a2 += f1.x * ns; a3 += f1.y * ns;
                a4 += f2.x * ns; a5 += f2.y * ns;
                a6 += f3.x * ns; a7 += f3.y * ns;
            }
        } else {
            for (int jb = 0; jb < m; jb += 2) {
                int  j   = jb + g;
                bool act = (j < m);
                int  s   = __shfl_sync(FULL, c, act ? j : 0);
                float ns = act ? g_dinv[s] * di : 0.f;
                uint4 u  = hv[s * 16 + l];
                float2 f0 = __half22float2(*reinterpret_cast<__half2*>(&u.x));
                float2 f1 = __half22float2(*reinterpret_cast<__half2*>(&u.y));
                float2 f2 = __half22float2(*reinterpret_cast<__half2*>(&u.z));
                float2 f3 = __half22float2(*reinterpret_cast<__half2*>(&u.w));
                a0 += f0.x * ns; a1 += f0.y * ns;
                a2 += f1.x * ns; a3 += f1.y * ns;
                a4 += f2.x * ns; a5 += f2.y * ns;
                a6 += f3.x * ns; a7 += f3.y * ns;
            }
        }
    }
    // reduce across the 2 groups
    a0 += __shfl_xor_sync(FULL, a0, 16);
    a1 += __shfl_xor_sync(FULL, a1, 16);
    a2 += __shfl_xor_sync(FULL, a2, 16);
    a3 += __shfl_xor_sync(FULL, a3, 16);
    a4 += __shfl_xor_sync(FULL, a4, 16);
    a5 += __shfl_xor_sync(FULL, a5, 16);
    a6 += __shfl_xor_sync(FULL, a6, 16);
    a7 += __shfl_xor_sync(FULL, a7, 16);
    if (g == 0) {
        uint4 u = hv[w * 16 + l];                    // self loop
        float sw = di * di;
        float2 f0 = __half22float2(*reinterpret_cast<__half2*>(&u.x));
        float2 f1 = __half22float2(*reinterpret_cast<__half2*>(&u.y));
        float2 f2 = __half22float2(*reinterpret_cast<__half2*>(&u.z));
        float2 f3 = __half22float2(*reinterpret_cast<__half2*>(&u.w));
        a0 += f0.x * sw; a1 += f0.y * sw;
        a2 += f1.x * sw; a3 += f1.y * sw;
        a4 += f2.x * sw; a5 += f2.y * sw;
        a6 += f3.x * sw; a7 += f3.y * sw;
        float4* dst = reinterpret_cast<float4*>(&g_agg2[w * HID + l * 8]);
        dst[0] = make_float4(a0, a1, a2, a3);
        dst[1] = make_float4(a4, a5, a6, a7);
    }
}

// ---------------- 6b) overflow fallback for layer-2 agg (normally empty) ----------------
__global__ void k_ovf2() {
    int nov = min(g_ovcnt, OVMAX);
    int lane = threadIdx.x & 31;
    int warp = (blockIdx.x * 256 + threadIdx.x) >> 5;
    int nw   = (gridDim.x * 256) >> 5;
    const uint2* hv = reinterpret_cast<const uint2*>(g_h1h);
    for (int i = warp; i < nov; i += nw) {
        int2 e = g_ov[i];
        float wgt = g_dinv[e.y] * g_dinv[e.x];
        uint2 u = hv[e.y * 32 + lane];
        float2 ul = __half22float2(*reinterpret_cast<__half2*>(&u.x));
        float2 uh = __half22float2(*reinterpret_cast<__half2*>(&u.y));
        atomicAdd(&g_agg2[e.x * HID + lane * 4],     ul.x * wgt);
        atomicAdd(&g_agg2[e.x * HID + lane * 4 + 1], ul.y * wgt);
        atomicAdd(&g_agg2[e.x * HID + lane * 4 + 2], uh.x * wgt);
        atomicAdd(&g_agg2[e.x * HID + lane * 4 + 3], uh.y * wgt);
    }
}

// ---------------- 7) GEMM2: out = agg2 @ W2 + b2, 4x8 FFMA2 ----------------
__global__ void __launch_bounds__(256) k_gemm2(const float* __restrict__ W2,
                                               const float* __restrict__ b2,
                                               float* __restrict__ out) {
    __shared__ float As[TILE * HID];     // 32 KB
    int tid  = threadIdx.x;
    int tcol = (tid & 15) * 8;
    int trow = (tid >> 4) * 4;
    int row0 = blockIdx.x * TILE;
    u64 bias[4];
    bias[0] = packf2(__ldg(&b2[tcol]),     __ldg(&b2[tcol + 1]));
    bias[1] = packf2(__ldg(&b2[tcol + 2]), __ldg(&b2[tcol + 3]));
    bias[2] = packf2(__ldg(&b2[tcol + 4]), __ldg(&b2[tcol + 5]));
    bias[3] = packf2(__ldg(&b2[tcol + 6]), __ldg(&b2[tcol + 7]));

#pragma unroll
    for (int i = 0; i < 8; i++) {
        int idx = tid + i * 256;
        int gr  = row0 + (idx >> 5);
        reinterpret_cast<float4*>(As)[idx] = (gr < NN)
            ? reinterpret_cast<const float4*>(g_agg2)[gr * 32 + (idx & 31)]
            : make_float4(0.f, 0.f, 0.f, 0.f);
    }
    __syncthreads();

    u64 acc[4][4];
#pragma unroll
    for (int r = 0; r < 4; r++)
#pragma unroll
        for (int c = 0; c < 4; c++) acc[r][c] = bias[c];
#pragma unroll 4
    for (int k = 0; k < HID; k++) {
        ulonglong2 wa = __ldg(reinterpret_cast<const ulonglong2*>(&W2[k * HID + tcol]));
        ulonglong2 wb = __ldg(reinterpret_cast<const ulonglong2*>(&W2[k * HID + tcol + 4]));
#pragma unroll
        for (int r = 0; r < 4; r++) {
            u64 a = dup2(As[(trow + r) * HID + k]);
            ffma2(acc[r][0], a, wa.x); ffma2(acc[r][1], a, wa.y);
            ffma2(acc[r][2], a, wb.x); ffma2(acc[r][3], a, wb.y);
        }
    }
#pragma unroll
    for (int r = 0; r < 4; r++) {
        int gr = row0 + trow + r;
        if (gr < NN) {
            float2 p0 = unpackf2(acc[r][0]);
            float2 p1 = unpackf2(acc[r][1]);
            float2 p2 = unpackf2(acc[r][2]);
            float2 p3 = unpackf2(acc[r][3]);
            *reinterpret_cast<float4*>(&out[gr * HID + tcol])     = make_float4(p0.x, p0.y, p1.x, p1.y);
            *reinterpret_cast<float4*>(&out[gr * HID + tcol + 4]) = make_float4(p2.x, p2.y, p3.x, p3.y);
        }
    }
}

// ---------------- host launcher ----------------
extern "C" void kernel_launch(void* const* d_in, const int* in_sizes, int n_in,
                              void* d_out, int out_size) {
    const int*   ei  = (const int*)d_in[1];
    const float* emb = (const float*)d_in[2];
    const float* W1  = (const float*)d_in[3];
    const float* b1  = (const float*)d_in[4];
    const float* W2  = (const float*)d_in[5];
    const float* b2  = (const float*)d_in[6];
    float* out = (float*)d_out;

    const int NT = (NN + TILE - 1) / TILE;           // 782
    k_init    <<<(NN + 255) / 256, 256>>>();
    k_scatter <<<(ER / 4 + 255) / 256, 256>>>(ei);
    k_dinv    <<<(NN + 255) / 256, 256>>>();
    k_agg_emb <<<(NN * 32) / 256, 256>>>(emb);
    k_ovf1    <<<2, 256>>>(emb);
    k_gemm1   <<<NT, 256>>>(W1, b1);
    k_agg_h1  <<<(NN * 32) / 256, 256>>>();
    k_ovf2    <<<2, 256>>>();
    k_gemm2   <<<NT, 256>>>(W2, b2, out);
}

// round 13
// speedup vs baseline: 1.2658x; 1.0345x over previous
#include <cuda_runtime.h>
#include <cuda_fp16.h>

#define NN   50000
#define ER   1600000
#define EMB  32
#define HID  128
#define TILE 64
#define CAP  128          // bucket capacity per node (E[deg]=32, P(>128)~1e-40)
#define OVMAX 8192
#define FULL 0xffffffffu

typedef unsigned long long u64;

// ---- packed f32x2 helpers (sm_103a FFMA2 path, PTX-only) ----
__device__ __forceinline__ u64 dup2(float a) {
    u64 r; asm("mov.b64 %0, {%1, %1};" : "=l"(r) : "f"(a)); return r;
}
__device__ __forceinline__ u64 packf2(float a, float b) {
    u64 r; asm("mov.b64 %0, {%1, %2};" : "=l"(r) : "f"(a), "f"(b)); return r;
}
__device__ __forceinline__ void ffma2(u64& d, u64 a, u64 b) {
    asm("fma.rn.f32x2 %0, %1, %2, %0;" : "+l"(d) : "l"(a), "l"(b));
}
__device__ __forceinline__ float2 unpackf2(u64 v) {
    float2 r; asm("mov.b64 {%0, %1}, %2;" : "=f"(r.x), "=f"(r.y) : "l"(v)); return r;
}

// ---------------- device scratch (static, no cudaMalloc; 16B-aligned for LDG.128) ----------------
__device__ int    g_cursor[NN];
__device__ float  g_dinv[NN];
__device__ __align__(16) int    g_col[NN * CAP];     // 25.6 MB direct buckets
__device__ int    g_ovcnt;
__device__ int2   g_ov[OVMAX];
__device__ __align__(16) float  g_xs[NN * EMB];      //  6.4 MB  (dinv-scaled emb)
__device__ __align__(16) float  g_aggemb[NN * EMB];  //  6.4 MB
__device__ __align__(16) __half g_h1h[NN * HID];     // 12.8 MB  (dinv-scaled hidden)
__device__ __align__(16) float  g_agg2[NN * HID];    // 25.6 MB

// ---------------- 1) init ----------------
__global__ void k_init() {
    int i = blockIdx.x * 256 + threadIdx.x;
    if (i < NN) g_cursor[i] = 0;
    if (i == 0) g_ovcnt = 0;
}

// ---------------- 2) direct-bucket scatter (4 edges/thread, MLP=4) ----------------
__global__ void k_scatter(const int* __restrict__ ei) {
    int t = blockIdx.x * 256 + threadIdx.x;          // t < ER/4
    if (t >= ER / 4) return;
    int4 s4 = reinterpret_cast<const int4*>(ei)[t];
    int4 d4 = reinterpret_cast<const int4*>(ei + ER)[t];
    int p0 = atomicAdd(&g_cursor[d4.x], 1);
    int p1 = atomicAdd(&g_cursor[d4.y], 1);
    int p2 = atomicAdd(&g_cursor[d4.z], 1);
    int p3 = atomicAdd(&g_cursor[d4.w], 1);
    if (p0 < CAP) g_col[d4.x * CAP + p0] = s4.x;
    else { int o = atomicAdd(&g_ovcnt, 1); if (o < OVMAX) g_ov[o] = make_int2(d4.x, s4.x); }
    if (p1 < CAP) g_col[d4.y * CAP + p1] = s4.y;
    else { int o = atomicAdd(&g_ovcnt, 1); if (o < OVMAX) g_ov[o] = make_int2(d4.y, s4.y); }
    if (p2 < CAP) g_col[d4.z * CAP + p2] = s4.z;
    else { int o = atomicAdd(&g_ovcnt, 1); if (o < OVMAX) g_ov[o] = make_int2(d4.z, s4.z); }
    if (p3 < CAP) g_col[d4.w * CAP + p3] = s4.w;
    else { int o = atomicAdd(&g_ovcnt, 1); if (o < OVMAX) g_ov[o] = make_int2(d4.w, s4.w); }
}

// ---------------- 3) dinv from final cursor counts ----------------
__global__ void k_dinv() {
    int i = blockIdx.x * 256 + threadIdx.x;
    if (i < NN) g_dinv[i] = rsqrtf((float)(g_cursor[i] + 1));   // +1 self loop
}

// ---------------- 3b) xs = dinv * emb (float4 per thread, coalesced) ----------------
__global__ void k_scale(const float* __restrict__ emb) {
    int t = blockIdx.x * 256 + threadIdx.x;          // t < NN*8
    if (t >= NN * (EMB / 4)) return;
    float d = g_dinv[t >> 3];
    float4 v = reinterpret_cast<const float4*>(emb)[t];
    v.x *= d; v.y *= d; v.z *= d; v.w *= d;
    reinterpret_cast<float4*>(g_xs)[t] = v;
}

// ---------------- 4) aggregate embeddings: unweighted sum of xs, scale by di ----------------
// lane = 8*g + l : group g handles edge jb+g; sublane l owns dims [4l, 4l+4).
__global__ void __launch_bounds__(256) k_agg_emb() {
    int w    = (blockIdx.x * 256 + threadIdx.x) >> 5;
    int lane = threadIdx.x & 31;
    int g    = lane >> 3;
    int l    = lane & 7;
    float di = g_dinv[w];
    float4 acc = make_float4(0.f, 0.f, 0.f, 0.f);
    int cnt = min(g_cursor[w], CAP);
    const int* cb = g_col + w * CAP;
    for (int base = 0; base < cnt; base += 32) {
        int c = cb[base + lane];                     // coalesced 128B
        int m = min(32, cnt - base);                 // warp-uniform
        if (m == 32) {
#pragma unroll 4
            for (int jb = 0; jb < 32; jb += 4) {
                int    s = __shfl_sync(FULL, c, jb + g);
                float4 r = *reinterpret_cast<const float4*>(&g_xs[s * EMB + l * 4]);
                acc.x += r.x; acc.y += r.y; acc.z += r.z; acc.w += r.w;
            }
        } else {
            for (int jb = 0; jb < m; jb += 4) {
                int  j   = jb + g;
                bool act = (j < m);
                int  s   = __shfl_sync(FULL, c, act ? j : 0);   // s always valid
                float4 r = *reinterpret_cast<const float4*>(&g_xs[s * EMB + l * 4]);
                if (act) { acc.x += r.x; acc.y += r.y; acc.z += r.z; acc.w += r.w; }
            }
        }
    }
    // reduce across the 4 groups (lanes differing in bits 3,4)
#pragma unroll
    for (int off = 8; off <= 16; off <<= 1) {
        acc.x += __shfl_xor_sync(FULL, acc.x, off);
        acc.y += __shfl_xor_sync(FULL, acc.y, off);
        acc.z += __shfl_xor_sync(FULL, acc.z, off);
        acc.w += __shfl_xor_sync(FULL, acc.w, off);
    }
    if (g == 0) {
        float4 v = *reinterpret_cast<const float4*>(&g_xs[w * EMB + l * 4]);  // self loop
        acc.x = (acc.x + v.x) * di;
        acc.y = (acc.y + v.y) * di;
        acc.z = (acc.z + v.z) * di;
        acc.w = (acc.w + v.w) * di;
        *reinterpret_cast<float4*>(&g_aggemb[w * EMB + l * 4]) = acc;
    }
}

// ---------------- 4b) overflow fallback for layer-1 agg (normally empty) ----------------
__global__ void k_ovf1() {
    int nov = min(g_ovcnt, OVMAX);
    int lane = threadIdx.x & 31;
    int warp = (blockIdx.x * 256 + threadIdx.x) >> 5;
    int nw   = (gridDim.x * 256) >> 5;
    for (int i = warp; i < nov; i += nw) {
        int2 e = g_ov[i];                            // (dst, src)
        atomicAdd(&g_aggemb[e.x * EMB + lane], g_xs[e.y * EMB + lane] * g_dinv[e.x]);
    }
}

// ---------------- 5) GEMM1: h1s = dinv * relu(aggemb @ W1 + b1) -> fp16 ----------------
__global__ void __launch_bounds__(256) k_gemm1(const float* __restrict__ W1,
                                               const float* __restrict__ b1) {
    __shared__ float As[TILE * EMB];     // 8 KB
    int tid  = threadIdx.x;
    int tcol = (tid & 15) * 8;
    int trow = (tid >> 4) * 4;
    int row0 = blockIdx.x * TILE;
    u64 bias[4];
    bias[0] = packf2(__ldg(&b1[tcol]),     __ldg(&b1[tcol + 1]));
    bias[1] = packf2(__ldg(&b1[tcol + 2]), __ldg(&b1[tcol + 3]));
    bias[2] = packf2(__ldg(&b1[tcol + 4]), __ldg(&b1[tcol + 5]));
    bias[3] = packf2(__ldg(&b1[tcol + 6]), __ldg(&b1[tcol + 7]));

#pragma unroll
    for (int i = 0; i < 2; i++) {
        int idx = tid + i * 256;
        int gr  = row0 + (idx >> 3);
        reinterpret_cast<float4*>(As)[idx] = (gr < NN)
            ? reinterpret_cast<const float4*>(g_aggemb)[gr * 8 + (idx & 7)]
            : make_float4(0.f, 0.f, 0.f, 0.f);
    }
    __syncthreads();

    u64 acc[4][4];
#pragma unroll
    for (int r = 0; r < 4; r++)
#pragma unroll
        for (int c = 0; c < 4; c++) acc[r][c] = bias[c];
#pragma unroll
    for (int k = 0; k < EMB; k++) {
        ulonglong2 wa = __ldg(reinterpret_cast<const ulonglong2*>(&W1[k * HID + tcol]));
        ulonglong2 wb = __ldg(reinterpret_cast<const ulonglong2*>(&W1[k * HID + tcol + 4]));
#pragma unroll
        for (int r = 0; r < 4; r++) {
            u64 a = dup2(As[(trow + r) * EMB + k]);
            ffma2(acc[r][0], a, wa.x); ffma2(acc[r][1], a, wa.y);
            ffma2(acc[r][2], a, wb.x); ffma2(acc[r][3], a, wb.y);
        }
    }
#pragma unroll
    for (int r = 0; r < 4; r++) {
        int gr = row0 + trow + r;
        if (gr < NN) {
            float d = g_dinv[gr];
            float2 p0 = unpackf2(acc[r][0]);
            float2 p1 = unpackf2(acc[r][1]);
            float2 p2 = unpackf2(acc[r][2]);
            float2 p3 = unpackf2(acc[r][3]);
            __half2 h0 = __floats2half2_rn(fmaxf(p0.x, 0.f) * d, fmaxf(p0.y, 0.f) * d);
            __half2 h1 = __floats2half2_rn(fmaxf(p1.x, 0.f) * d, fmaxf(p1.y, 0.f) * d);
            __half2 h2 = __floats2half2_rn(fmaxf(p2.x, 0.f) * d, fmaxf(p2.y, 0.f) * d);
            __half2 h3 = __floats2half2_rn(fmaxf(p3.x, 0.f) * d, fmaxf(p3.y, 0.f) * d);
            uint4 st;
            st.x = *reinterpret_cast<unsigned*>(&h0);
            st.y = *reinterpret_cast<unsigned*>(&h1);
            st.z = *reinterpret_cast<unsigned*>(&h2);
            st.w = *reinterpret_cast<unsigned*>(&h3);
            *reinterpret_cast<uint4*>(&g_h1h[gr * HID + tcol]) = st;
        }
    }
}

// ---------------- 6) aggregate h1s: unweighted fp16 sum, scale by di ----------------
// lane = 16*g + l : group g handles edge jb+g; sublane l owns dims [8l, 8l+8).
__global__ void __launch_bounds__(256) k_agg_h1() {
    int w    = (blockIdx.x * 256 + threadIdx.x) >> 5;
    int lane = threadIdx.x & 31;
    int g    = lane >> 4;
    int l    = lane & 15;
    float di = g_dinv[w];
    float a0 = 0.f, a1 = 0.f, a2 = 0.f, a3 = 0.f,
          a4 = 0.f, a5 = 0.f, a6 = 0.f, a7 = 0.f;
    int cnt = min(g_cursor[w], CAP);
    const int* cb = g_col + w * CAP;
    const uint4* hv = reinterpret_cast<const uint4*>(g_h1h);   // 8 halves / uint4
    for (int base = 0; base < cnt; base += 32) {
        int c = cb[base + lane];
        int m = min(32, cnt - base);                 // warp-uniform
        if (m == 32) {
#pragma unroll 4
            for (int jb = 0; jb < 32; jb += 2) {
                int   s = __shfl_sync(FULL, c, jb + g);
                uint4 u = hv[s * 16 + l];
                float2 f0 = __half22float2(*reinterpret_cast<__half2*>(&u.x));
                float2 f1 = __half22float2(*reinterpret_cast<__half2*>(&u.y));
                float2 f2 = __half22float2(*reinterpret_cast<__half2*>(&u.z));
                float2 f3 = __half22float2(*reinterpret_cast<__half2*>(&u.w));
                a0 += f0.x; a1 += f0.y; a2 += f1.x; a3 += f1.y;
                a4 += f2.x; a5 += f2.y; a6 += f3.x; a7 += f3.y;
            }
        } else {
            for (int jb = 0; jb < m; jb += 2) {
                int  j   = jb + g;
                bool act = (j < m);
                int  s   = __shfl_sync(FULL, c, act ? j : 0);
                uint4 u  = hv[s * 16 + l];
                float2 f0 = __half22float2(*reinterpret_cast<__half2*>(&u.x));
                float2 f1 = __half22float2(*reinterpret_cast<__half2*>(&u.y));
                float2 f2 = __half22float2(*reinterpret_cast<__half2*>(&u.z));
                float2 f3 = __half22float2(*reinterpret_cast<__half2*>(&u.w));
                if (act) {
                    a0 += f0.x; a1 += f0.y; a2 += f1.x; a3 += f1.y;
                    a4 += f2.x; a5 += f2.y; a6 += f3.x; a7 += f3.y;
                }
            }
        }
    }
    // reduce across the 2 groups
    a0 += __shfl_xor_sync(FULL, a0, 16);
    a1 += __shfl_xor_sync(FULL, a1, 16);
    a2 += __shfl_xor_sync(FULL, a2, 16);
    a3 += __shfl_xor_sync(FULL, a3, 16);
    a4 += __shfl_xor_sync(FULL, a4, 16);
    a5 += __shfl_xor_sync(FULL, a5, 16);
    a6 += __shfl_xor_sync(FULL, a6, 16);
    a7 += __shfl_xor_sync(FULL, a7, 16);
    if (g == 0) {
        uint4 u = hv[w * 16 + l];                    // self loop
        float2 f0 = __half22float2(*reinterpret_cast<__half2*>(&u.x));
        float2 f1 = __half22float2(*reinterpret_cast<__half2*>(&u.y));
        float2 f2 = __half22float2(*reinterpret_cast<__half2*>(&u.z));
        float2 f3 = __half22float2(*reinterpret_cast<__half2*>(&u.w));
        a0 = (a0 + f0.x) * di; a1 = (a1 + f0.y) * di;
        a2 = (a2 + f1.x) * di; a3 = (a3 + f1.y) * di;
        a4 = (a4 + f2.x) * di; a5 = (a5 + f2.y) * di;
        a6 = (a6 + f3.x) * di; a7 = (a7 + f3.y) * di;
        float4* dst = reinterpret_cast<float4*>(&g_agg2[w * HID + l * 8]);
        dst[0] = make_float4(a0, a1, a2, a3);
        dst[1] = make_float4(a4, a5, a6, a7);
    }
}

// ---------------- 6b) overflow fallback for layer-2 agg (normally empty) ----------------
__global__ void k_ovf2() {
    int nov = min(g_ovcnt, OVMAX);
    int lane = threadIdx.x & 31;
    int warp = (blockIdx.x * 256 + threadIdx.x) >> 5;
    int nw   = (gridDim.x * 256) >> 5;
    const uint2* hv = reinterpret_cast<const uint2*>(g_h1h);
    for (int i = warp; i < nov; i += nw) {
        int2 e = g_ov[i];                            // (dst, src)
        float wgt = g_dinv[e.x];
        uint2 u = hv[e.y * 32 + lane];
        float2 ul = __half22float2(*reinterpret_cast<__half2*>(&u.x));
        float2 uh = __half22float2(*reinterpret_cast<__half2*>(&u.y));
        atomicAdd(&g_agg2[e.x * HID + lane * 4],     ul.x * wgt);
        atomicAdd(&g_agg2[e.x * HID + lane * 4 + 1], ul.y * wgt);
        atomicAdd(&g_agg2[e.x * HID + lane * 4 + 2], uh.x * wgt);
        atomicAdd(&g_agg2[e.x * HID + lane * 4 + 3], uh.y * wgt);
    }
}

// ---------------- 7) GEMM2: out = agg2 @ W2 + b2, 4x8 FFMA2 ----------------
__global__ void __launch_bounds__(256) k_gemm2(const float* __restrict__ W2,
                                               const float* __restrict__ b2,
                                               float* __restrict__ out) {
    __shared__ float As[TILE * HID];     // 32 KB
    int tid  = threadIdx.x;
    int tcol = (tid & 15) * 8;
    int trow = (tid >> 4) * 4;
    int row0 = blockIdx.x * TILE;
    u64 bias[4];
    bias[0] = packf2(__ldg(&b2[tcol]),     __ldg(&b2[tcol + 1]));
    bias[1] = packf2(__ldg(&b2[tcol + 2]), __ldg(&b2[tcol + 3]));
    bias[2] = packf2(__ldg(&b2[tcol + 4]), __ldg(&b2[tcol + 5]));
    bias[3] = packf2(__ldg(&b2[tcol + 6]), __ldg(&b2[tcol + 7]));

#pragma unroll
    for (int i = 0; i < 8; i++) {
        int idx = tid + i * 256;
        int gr  = row0 + (idx >> 5);
        reinterpret_cast<float4*>(As)[idx] = (gr < NN)
            ? reinterpret_cast<const float4*>(g_agg2)[gr * 32 + (idx & 31)]
            : make_float4(0.f, 0.f, 0.f, 0.f);
    }
    __syncthreads();

    u64 acc[4][4];
#pragma unroll
    for (int r = 0; r < 4; r++)
#pragma unroll
        for (int c = 0; c < 4; c++) acc[r][c] = bias[c];
#pragma unroll 4
    for (int k = 0; k < HID; k++) {
        ulonglong2 wa = __ldg(reinterpret_cast<const ulonglong2*>(&W2[k * HID + tcol]));
        ulonglong2 wb = __ldg(reinterpret_cast<const ulonglong2*>(&W2[k * HID + tcol + 4]));
#pragma unroll
        for (int r = 0; r < 4; r++) {
            u64 a = dup2(As[(trow + r) * HID + k]);
            ffma2(acc[r][0], a, wa.x); ffma2(acc[r][1], a, wa.y);
            ffma2(acc[r][2], a, wb.x); ffma2(acc[r][3], a, wb.y);
        }
    }
#pragma unroll
    for (int r = 0; r < 4; r++) {
        int gr = row0 + trow + r;
        if (gr < NN) {
            float2 p0 = unpackf2(acc[r][0]);
            float2 p1 = unpackf2(acc[r][1]);
            float2 p2 = unpackf2(acc[r][2]);
            float2 p3 = unpackf2(acc[r][3]);
            *reinterpret_cast<float4*>(&out[gr * HID + tcol])     = make_float4(p0.x, p0.y, p1.x, p1.y);
            *reinterpret_cast<float4*>(&out[gr * HID + tcol + 4]) = make_float4(p2.x, p2.y, p3.x, p3.y);
        }
    }
}

// ---------------- host launcher ----------------
extern "C" void kernel_launch(void* const* d_in, const int* in_sizes, int n_in,
                              void* d_out, int out_size) {
    const int*   ei  = (const int*)d_in[1];
    const float* emb = (const float*)d_in[2];
    const float* W1  = (const float*)d_in[3];
    const float* b1  = (const float*)d_in[4];
    const float* W2  = (const float*)d_in[5];
    const float* b2  = (const float*)d_in[6];
    float* out = (float*)d_out;

    const int NT = (NN + TILE - 1) / TILE;           // 782
    k_init    <<<(NN + 255) / 256, 256>>>();
    k_scatter <<<(ER / 4 + 255) / 256, 256>>>(ei);
    k_dinv    <<<(NN + 255) / 256, 256>>>();
    k_scale   <<<(NN * (EMB / 4) + 255) / 256, 256>>>(emb);
    k_agg_emb <<<(NN * 32) / 256, 256>>>();
    k_ovf1    <<<2, 256>>>();
    k_gemm1   <<<NT, 256>>>(W1, b1);
    k_agg_h1  <<<(NN * 32) / 256, 256>>>();
    k_ovf2    <<<2, 256>>>();
    k_gemm2   <<<NT, 256>>>(W2, b2, out);
}

// round 14
// speedup vs baseline: 1.2799x; 1.0112x over previous
#include <cuda_runtime.h>
#include <cuda_fp16.h>

#define NN   50000
#define ER   1600000
#define EMB  32
#define HID  128
#define TILE 64
#define CAP  128          // bucket capacity per node (E[deg]=32, P(>128)~1e-40)
#define OVMAX 8192
#define FULL 0xffffffffu

typedef unsigned long long u64;

// ---- packed f32x2 helpers (sm_103a FFMA2 path, PTX-only) ----
__device__ __forceinline__ u64 dup2(float a) {
    u64 r; asm("mov.b64 %0, {%1, %1};" : "=l"(r) : "f"(a)); return r;
}
__device__ __forceinline__ u64 packf2(float a, float b) {
    u64 r; asm("mov.b64 %0, {%1, %2};" : "=l"(r) : "f"(a), "f"(b)); return r;
}
__device__ __forceinline__ void ffma2(u64& d, u64 a, u64 b) {
    asm("fma.rn.f32x2 %0, %1, %2, %0;" : "+l"(d) : "l"(a), "l"(b));
}
__device__ __forceinline__ float2 unpackf2(u64 v) {
    float2 r; asm("mov.b64 {%0, %1}, %2;" : "=f"(r.x), "=f"(r.y) : "l"(v)); return r;
}

// ---------------- device scratch (static, no cudaMalloc; 16B-aligned for LDG.128) ----------------
__device__ int    g_cursor[NN];
__device__ float  g_dinv[NN];
__device__ __align__(16) int    g_col[NN * CAP];     // 25.6 MB direct buckets
__device__ int    g_ovcnt;
__device__ int2   g_ov[OVMAX];
__device__ __align__(16) float  g_xs[NN * EMB];      //  6.4 MB  (dinv-scaled emb)
__device__ __align__(16) float  g_aggemb[NN * EMB];  //  6.4 MB
__device__ __align__(16) __half g_h1h[NN * HID];     // 12.8 MB  (dinv-scaled hidden)
__device__ __align__(16) __half g_agg2h[NN * HID];   // 12.8 MB  (fp16 layer-2 aggregate)

// ---------------- 1) init ----------------
__global__ void k_init() {
    int i = blockIdx.x * 256 + threadIdx.x;
    if (i < NN) g_cursor[i] = 0;
    if (i == 0) g_ovcnt = 0;
}

// ---------------- 2) direct-bucket scatter (8 edges/thread, MLP=8) ----------------
__global__ void k_scatter(const int* __restrict__ ei) {
    int t = blockIdx.x * 256 + threadIdx.x;          // t < ER/8
    if (t >= ER / 8) return;
    int4 sa = reinterpret_cast<const int4*>(ei)[2 * t];
    int4 sb = reinterpret_cast<const int4*>(ei)[2 * t + 1];
    int4 da = reinterpret_cast<const int4*>(ei + ER)[2 * t];
    int4 db = reinterpret_cast<const int4*>(ei + ER)[2 * t + 1];
    int p0 = atomicAdd(&g_cursor[da.x], 1);
    int p1 = atomicAdd(&g_cursor[da.y], 1);
    int p2 = atomicAdd(&g_cursor[da.z], 1);
    int p3 = atomicAdd(&g_cursor[da.w], 1);
    int p4 = atomicAdd(&g_cursor[db.x], 1);
    int p5 = atomicAdd(&g_cursor[db.y], 1);
    int p6 = atomicAdd(&g_cursor[db.z], 1);
    int p7 = atomicAdd(&g_cursor[db.w], 1);
#define PUT(p, d, s) \
    if ((p) < CAP) g_col[(d) * CAP + (p)] = (s); \
    else { int o = atomicAdd(&g_ovcnt, 1); if (o < OVMAX) g_ov[o] = make_int2((d), (s)); }
    PUT(p0, da.x, sa.x) PUT(p1, da.y, sa.y) PUT(p2, da.z, sa.z) PUT(p3, da.w, sa.w)
    PUT(p4, db.x, sb.x) PUT(p5, db.y, sb.y) PUT(p6, db.z, sb.z) PUT(p7, db.w, sb.w)
#undef PUT
}

// ---------------- 3) fused dinv + xs = dinv * emb ----------------
__global__ void k_dinv_scale(const float* __restrict__ emb) {
    int t = blockIdx.x * 256 + threadIdx.x;          // t < NN*8
    if (t >= NN * (EMB / 4)) return;
    int n = t >> 3;
    float d = rsqrtf((float)(g_cursor[n] + 1));      // +1 self loop
    if ((t & 7) == 0) g_dinv[n] = d;
    float4 v = reinterpret_cast<const float4*>(emb)[t];
    v.x *= d; v.y *= d; v.z *= d; v.w *= d;
    reinterpret_cast<float4*>(g_xs)[t] = v;
}

// ---------------- 4) aggregate embeddings: unweighted sum of xs, scale by di ----------------
// lane = 8*g + l : group g handles edge jb+g; sublane l owns dims [4l, 4l+4).
__global__ void __launch_bounds__(256) k_agg_emb() {
    int w    = (blockIdx.x * 256 + threadIdx.x) >> 5;
    int lane = threadIdx.x & 31;
    int g    = lane >> 3;
    int l    = lane & 7;
    float di = g_dinv[w];
    float4 acc = make_float4(0.f, 0.f, 0.f, 0.f);
    int cnt = min(g_cursor[w], CAP);
    const int* cb = g_col + w * CAP;
    for (int base = 0; base < cnt; base += 32) {
        int c = cb[base + lane];                     // coalesced 128B
        int m = min(32, cnt - base);                 // warp-uniform
        if (m == 32) {
#pragma unroll 4
            for (int jb = 0; jb < 32; jb += 4) {
                int    s = __shfl_sync(FULL, c, jb + g);
                float4 r = *reinterpret_cast<const float4*>(&g_xs[s * EMB + l * 4]);
                acc.x += r.x; acc.y += r.y; acc.z += r.z; acc.w += r.w;
            }
        } else {
            for (int jb = 0; jb < m; jb += 4) {
                int  j   = jb + g;
                bool act = (j < m);
                int  s   = __shfl_sync(FULL, c, act ? j : 0);   // s always valid
                float4 r = *reinterpret_cast<const float4*>(&g_xs[s * EMB + l * 4]);
                if (act) { acc.x += r.x; acc.y += r.y; acc.z += r.z; acc.w += r.w; }
            }
        }
    }
#pragma unroll
    for (int off = 8; off <= 16; off <<= 1) {
        acc.x += __shfl_xor_sync(FULL, acc.x, off);
        acc.y += __shfl_xor_sync(FULL, acc.y, off);
        acc.z += __shfl_xor_sync(FULL, acc.z, off);
        acc.w += __shfl_xor_sync(FULL, acc.w, off);
    }
    if (g == 0) {
        float4 v = *reinterpret_cast<const float4*>(&g_xs[w * EMB + l * 4]);  // self loop
        acc.x = (acc.x + v.x) * di;
        acc.y = (acc.y + v.y) * di;
        acc.z = (acc.z + v.z) * di;
        acc.w = (acc.w + v.w) * di;
        *reinterpret_cast<float4*>(&g_aggemb[w * EMB + l * 4]) = acc;
    }
}

// ---------------- 4b) overflow fallback for layer-1 agg (normally empty) ----------------
__global__ void k_ovf1() {
    int nov = min(g_ovcnt, OVMAX);
    int lane = threadIdx.x & 31;
    int warp = (blockIdx.x * 256 + threadIdx.x) >> 5;
    int nw   = (gridDim.x * 256) >> 5;
    for (int i = warp; i < nov; i += nw) {
        int2 e = g_ov[i];                            // (dst, src)
        atomicAdd(&g_aggemb[e.x * EMB + lane], g_xs[e.y * EMB + lane] * g_dinv[e.x]);
    }
}

// ---------------- 5) GEMM1: h1s = dinv * relu(aggemb @ W1 + b1) -> fp16 ----------------
__global__ void __launch_bounds__(256) k_gemm1(const float* __restrict__ W1,
                                               const float* __restrict__ b1) {
    __shared__ float As[TILE * EMB];     // 8 KB
    int tid  = threadIdx.x;
    int tcol = (tid & 15) * 8;
    int trow = (tid >> 4) * 4;
    int row0 = blockIdx.x * TILE;
    u64 bias[4];
    bias[0] = packf2(__ldg(&b1[tcol]),     __ldg(&b1[tcol + 1]));
    bias[1] = packf2(__ldg(&b1[tcol + 2]), __ldg(&b1[tcol + 3]));
    bias[2] = packf2(__ldg(&b1[tcol + 4]), __ldg(&b1[tcol + 5]));
    bias[3] = packf2(__ldg(&b1[tcol + 6]), __ldg(&b1[tcol + 7]));

#pragma unroll
    for (int i = 0; i < 2; i++) {
        int idx = tid + i * 256;
        int gr  = row0 + (idx >> 3);
        reinterpret_cast<float4*>(As)[idx] = (gr < NN)
            ? reinterpret_cast<const float4*>(g_aggemb)[gr * 8 + (idx & 7)]
            : make_float4(0.f, 0.f, 0.f, 0.f);
    }
    __syncthreads();

    u64 acc[4][4];
#pragma unroll
    for (int r = 0; r < 4; r++)
#pragma unroll
        for (int c = 0; c < 4; c++) acc[r][c] = bias[c];
#pragma unroll
    for (int k = 0; k < EMB; k++) {
        ulonglong2 wa = __ldg(reinterpret_cast<const ulonglong2*>(&W1[k * HID + tcol]));
        ulonglong2 wb = __ldg(reinterpret_cast<const ulonglong2*>(&W1[k * HID + tcol + 4]));
#pragma unroll
        for (int r = 0; r < 4; r++) {
            u64 a = dup2(As[(trow + r) * EMB + k]);
            ffma2(acc[r][0], a, wa.x); ffma2(acc[r][1], a, wa.y);
            ffma2(acc[r][2], a, wb.x); ffma2(acc[r][3], a, wb.y);
        }
    }
#pragma unroll
    for (int r = 0; r < 4; r++) {
        int gr = row0 + trow + r;
        if (gr < NN) {
            float d = g_dinv[gr];
            float2 p0 = unpackf2(acc[r][0]);
            float2 p1 = unpackf2(acc[r][1]);
            float2 p2 = unpackf2(acc[r][2]);
            float2 p3 = unpackf2(acc[r][3]);
            __half2 h0 = __floats2half2_rn(fmaxf(p0.x, 0.f) * d, fmaxf(p0.y, 0.f) * d);
            __half2 h1 = __floats2half2_rn(fmaxf(p1.x, 0.f) * d, fmaxf(p1.y, 0.f) * d);
            __half2 h2 = __floats2half2_rn(fmaxf(p2.x, 0.f) * d, fmaxf(p2.y, 0.f) * d);
            __half2 h3 = __floats2half2_rn(fmaxf(p3.x, 0.f) * d, fmaxf(p3.y, 0.f) * d);
            uint4 st;
            st.x = *reinterpret_cast<unsigned*>(&h0);
            st.y = *reinterpret_cast<unsigned*>(&h1);
            st.z = *reinterpret_cast<unsigned*>(&h2);
            st.w = *reinterpret_cast<unsigned*>(&h3);
            *reinterpret_cast<uint4*>(&g_h1h[gr * HID + tcol]) = st;
        }
    }
}

// ---------------- 6) aggregate h1s: unweighted fp16 sum, scale by di -> fp16 ----------------
// lane = 16*g + l : group g handles edge jb+g; sublane l owns dims [8l, 8l+8).
__global__ void __launch_bounds__(256) k_agg_h1() {
    int w    = (blockIdx.x * 256 + threadIdx.x) >> 5;
    int lane = threadIdx.x & 31;
    int g    = lane >> 4;
    int l    = lane & 15;
    float di = g_dinv[w];
    float a0 = 0.f, a1 = 0.f, a2 = 0.f, a3 = 0.f,
          a4 = 0.f, a5 = 0.f, a6 = 0.f, a7 = 0.f;
    int cnt = min(g_cursor[w], CAP);
    const int* cb = g_col + w * CAP;
    const uint4* hv = reinterpret_cast<const uint4*>(g_h1h);   // 8 halves / uint4
    for (int base = 0; base < cnt; base += 32) {
        int c = cb[base + lane];
        int m = min(32, cnt - base);                 // warp-uniform
        if (m == 32) {
#pragma unroll 4
            for (int jb = 0; jb < 32; jb += 2) {
                int   s = __shfl_sync(FULL, c, jb + g);
                uint4 u = hv[s * 16 + l];
                float2 f0 = __half22float2(*reinterpret_cast<__half2*>(&u.x));
                float2 f1 = __half22float2(*reinterpret_cast<__half2*>(&u.y));
                float2 f2 = __half22float2(*reinterpret_cast<__half2*>(&u.z));
                float2 f3 = __half22float2(*reinterpret_cast<__half2*>(&u.w));
                a0 += f0.x; a1 += f0.y; a2 += f1.x; a3 += f1.y;
                a4 += f2.x; a5 += f2.y; a6 += f3.x; a7 += f3.y;
            }
        } else {
            for (int jb = 0; jb < m; jb += 2) {
                int  j   = jb + g;
                bool act = (j < m);
                int  s   = __shfl_sync(FULL, c, act ? j : 0);
                uint4 u  = hv[s * 16 + l];
                float2 f0 = __half22float2(*reinterpret_cast<__half2*>(&u.x));
                float2 f1 = __half22float2(*reinterpret_cast<__half2*>(&u.y));
                float2 f2 = __half22float2(*reinterpret_cast<__half2*>(&u.z));
                float2 f3 = __half22float2(*reinterpret_cast<__half2*>(&u.w));
                if (act) {
                    a0 += f0.x; a1 += f0.y; a2 += f1.x; a3 += f1.y;
                    a4 += f2.x; a5 += f2.y; a6 += f3.x; a7 += f3.y;
                }
            }
        }
    }
    a0 += __shfl_xor_sync(FULL, a0, 16);
    a1 += __shfl_xor_sync(FULL, a1, 16);
    a2 += __shfl_xor_sync(FULL, a2, 16);
    a3 += __shfl_xor_sync(FULL, a3, 16);
    a4 += __shfl_xor_sync(FULL, a4, 16);
    a5 += __shfl_xor_sync(FULL, a5, 16);
    a6 += __shfl_xor_sync(FULL, a6, 16);
    a7 += __shfl_xor_sync(FULL, a7, 16);
    if (g == 0) {
        uint4 u = hv[w * 16 + l];                    // self loop
        float2 f0 = __half22float2(*reinterpret_cast<__half2*>(&u.x));
        float2 f1 = __half22float2(*reinterpret_cast<__half2*>(&u.y));
        float2 f2 = __half22float2(*reinterpret_cast<__half2*>(&u.z));
        float2 f3 = __half22float2(*reinterpret_cast<__half2*>(&u.w));
        __half2 o0 = __floats2half2_rn((a0 + f0.x) * di, (a1 + f0.y) * di);
        __half2 o1 = __floats2half2_rn((a2 + f1.x) * di, (a3 + f1.y) * di);
        __half2 o2 = __floats2half2_rn((a4 + f2.x) * di, (a5 + f2.y) * di);
        __half2 o3 = __floats2half2_rn((a6 + f3.x) * di, (a7 + f3.y) * di);
        uint4 st;
        st.x = *reinterpret_cast<unsigned*>(&o0);
        st.y = *reinterpret_cast<unsigned*>(&o1);
        st.z = *reinterpret_cast<unsigned*>(&o2);
        st.w = *reinterpret_cast<unsigned*>(&o3);
        *reinterpret_cast<uint4*>(&g_agg2h[w * HID + l * 8]) = st;
    }
}

// ---------------- 6b) overflow fallback for layer-2 agg (normally empty) ----------------
__global__ void k_ovf2() {
    int nov = min(g_ovcnt, OVMAX);
    int lane = threadIdx.x & 31;
    int warp = (blockIdx.x * 256 + threadIdx.x) >> 5;
    int nw   = (gridDim.x * 256) >> 5;
    const uint2* hv = reinterpret_cast<const uint2*>(g_h1h);
    for (int i = warp; i < nov; i += nw) {
        int2 e = g_ov[i];                            // (dst, src)
        float wgt = g_dinv[e.x];
        uint2 u = hv[e.y * 32 + lane];
        float2 ul = __half22float2(*reinterpret_cast<__half2*>(&u.x));
        float2 uh = __half22float2(*reinterpret_cast<__half2*>(&u.y));
        __half2 d0 = __floats2half2_rn(ul.x * wgt, ul.y * wgt);
        __half2 d1 = __floats2half2_rn(uh.x * wgt, uh.y * wgt);
        atomicAdd(reinterpret_cast<__half2*>(&g_agg2h[e.x * HID + lane * 4]),     d0);
        atomicAdd(reinterpret_cast<__half2*>(&g_agg2h[e.x * HID + lane * 4 + 2]), d1);
    }
}

// ---------------- 7) GEMM2: out = agg2h @ W2 + b2, 4x8 FFMA2, fp16 A staging ----------------
__global__ void __launch_bounds__(256) k_gemm2(const float* __restrict__ W2,
                                               const float* __restrict__ b2,
                                               float* __restrict__ out) {
    __shared__ float As[TILE * HID];     // 32 KB
    int tid  = threadIdx.x;
    int tcol = (tid & 15) * 8;
    int trow = (tid >> 4) * 4;
    int row0 = blockIdx.x * TILE;
    u64 bias[4];
    bias[0] = packf2(__ldg(&b2[tcol]),     __ldg(&b2[tcol + 1]));
    bias[1] = packf2(__ldg(&b2[tcol + 2]), __ldg(&b2[tcol + 3]));
    bias[2] = packf2(__ldg(&b2[tcol + 4]), __ldg(&b2[tcol + 5]));
    bias[3] = packf2(__ldg(&b2[tcol + 6]), __ldg(&b2[tcol + 7]));

    // load 64x128 fp16 A tile (1024 uint4, 4 per thread), convert to fp32 smem
    const uint4* av = reinterpret_cast<const uint4*>(g_agg2h);   // 8 halves / uint4
#pragma unroll
    for (int i = 0; i < 4; i++) {
        int idx = tid + i * 256;                     // uint4 index, < 1024
        int gr  = row0 + (idx >> 4);
        uint4 u = (gr < NN) ? av[gr * 16 + (idx & 15)] : make_uint4(0, 0, 0, 0);
        float2 f0 = __half22float2(*reinterpret_cast<__half2*>(&u.x));
        float2 f1 = __half22float2(*reinterpret_cast<__half2*>(&u.y));
        float2 f2 = __half22float2(*reinterpret_cast<__half2*>(&u.z));
        float2 f3 = __half22float2(*reinterpret_cast<__half2*>(&u.w));
        float* dst = &As[(idx >> 4) * HID + (idx & 15) * 8];
        reinterpret_cast<float4*>(dst)[0] = make_float4(f0.x, f0.y, f1.x, f1.y);
        reinterpret_cast<float4*>(dst)[1] = make_float4(f2.x, f2.y, f3.x, f3.y);
    }
    __syncthreads();

    u64 acc[4][4];
#pragma unroll
    for (int r = 0; r < 4; r++)
#pragma unroll
        for (int c = 0; c < 4; c++) acc[r][c] = bias[c];
#pragma unroll 4
    for (int k = 0; k < HID; k++) {
        ulonglong2 wa = __ldg(reinterpret_cast<const ulonglong2*>(&W2[k * HID + tcol]));
        ulonglong2 wb = __ldg(reinterpret_cast<const ulonglong2*>(&W2[k * HID + tcol + 4]));
#pragma unroll
        for (int r = 0; r < 4; r++) {
            u64 a = dup2(As[(trow + r) * HID + k]);
            ffma2(acc[r][0], a, wa.x); ffma2(acc[r][1], a, wa.y);
            ffma2(acc[r][2], a, wb.x); ffma2(acc[r][3], a, wb.y);
        }
    }
#pragma unroll
    for (int r = 0; r < 4; r++) {
        int gr = row0 + trow + r;
        if (gr < NN) {
            float2 p0 = unpackf2(acc[r][0]);
            float2 p1 = unpackf2(acc[r][1]);
            float2 p2 = unpackf2(acc[r][2]);
            float2 p3 = unpackf2(acc[r][3]);
            *reinterpret_cast<float4*>(&out[gr * HID + tcol])     = make_float4(p0.x, p0.y, p1.x, p1.y);
            *reinterpret_cast<float4*>(&out[gr * HID + tcol + 4]) = make_float4(p2.x, p2.y, p3.x, p3.y);
        }
    }
}

// ---------------- host launcher ----------------
extern "C" void kernel_launch(void* const* d_in, const int* in_sizes, int n_in,
                              void* d_out, int out_size) {
    const int*   ei  = (const int*)d_in[1];
    const float* emb = (const float*)d_in[2];
    const float* W1  = (const float*)d_in[3];
    const float* b1  = (const float*)d_in[4];
    const float* W2  = (const float*)d_in[5];
    const float* b2  = (const float*)d_in[6];
    float* out = (float*)d_out;

    const int NT = (NN + TILE - 1) / TILE;           // 782
    k_init       <<<(NN + 255) / 256, 256>>>();
    k_scatter    <<<(ER / 8 + 255) / 256, 256>>>(ei);
    k_dinv_scale <<<(NN * (EMB / 4) + 255) / 256, 256>>>(emb);
    k_agg_emb    <<<(NN * 32) / 256, 256>>>();
    k_ovf1       <<<2, 256>>>();
    k_gemm1      <<<NT, 256>>>(W1, b1);
    k_agg_h1     <<<(NN * 32) / 256, 256>>>();
    k_ovf2       <<<2, 256>>>();
    k_gemm2      <<<NT, 256>>>(W2, b2, out);
}

// round 15
// speedup vs baseline: 1.2831x; 1.0025x over previous
#include <cuda_runtime.h>
#include <cuda_fp16.h>

#define NN   50000
#define ER   1600000
#define EMB  32
#define HID  128
#define TILE 64
#define CAP  128          // bucket capacity per node (E[deg]=32, P(>128)~1e-40)
#define OVMAX 8192
#define FULL 0xffffffffu

typedef unsigned long long u64;

// ---- packed f32x2 helpers (sm_103a FFMA2 path, PTX-only) ----
__device__ __forceinline__ u64 dup2(float a) {
    u64 r; asm("mov.b64 %0, {%1, %1};" : "=l"(r) : "f"(a)); return r;
}
__device__ __forceinline__ u64 packf2(float a, float b) {
    u64 r; asm("mov.b64 %0, {%1, %2};" : "=l"(r) : "f"(a), "f"(b)); return r;
}
__device__ __forceinline__ void ffma2(u64& d, u64 a, u64 b) {
    asm("fma.rn.f32x2 %0, %1, %2, %0;" : "+l"(d) : "l"(a), "l"(b));
}
__device__ __forceinline__ float2 unpackf2(u64 v) {
    float2 r; asm("mov.b64 {%0, %1}, %2;" : "=f"(r.x), "=f"(r.y) : "l"(v)); return r;
}

// ---------------- device scratch (static, no cudaMalloc; 16B-aligned for LDG.128) ----------------
__device__ int    g_cursor[NN];
__device__ float  g_dinv[NN];
__device__ __align__(16) int    g_col[NN * CAP];     // 25.6 MB direct buckets
__device__ int    g_ovcnt;
__device__ int2   g_ov[OVMAX];
__device__ __align__(16) __half g_xsh[NN * EMB];     //  3.2 MB  (fp16 dinv-scaled emb)
__device__ __align__(16) float  g_aggemb[NN * EMB];  //  6.4 MB
__device__ __align__(16) __half g_h1h[NN * HID];     // 12.8 MB  (fp16 dinv-scaled hidden)
__device__ __align__(16) __half g_agg2h[NN * HID];   // 12.8 MB  (fp16 layer-2 aggregate)

// ---------------- 1) init ----------------
__global__ void k_init() {
    int i = blockIdx.x * 256 + threadIdx.x;
    if (i < NN) g_cursor[i] = 0;
    if (i == 0) g_ovcnt = 0;
}

// ---------------- 2) direct-bucket scatter (8 edges/thread, MLP=8) ----------------
__global__ void k_scatter(const int* __restrict__ ei) {
    int t = blockIdx.x * 256 + threadIdx.x;          // t < ER/8
    if (t >= ER / 8) return;
    int4 sa = reinterpret_cast<const int4*>(ei)[2 * t];
    int4 sb = reinterpret_cast<const int4*>(ei)[2 * t + 1];
    int4 da = reinterpret_cast<const int4*>(ei + ER)[2 * t];
    int4 db = reinterpret_cast<const int4*>(ei + ER)[2 * t + 1];
    int p0 = atomicAdd(&g_cursor[da.x], 1);
    int p1 = atomicAdd(&g_cursor[da.y], 1);
    int p2 = atomicAdd(&g_cursor[da.z], 1);
    int p3 = atomicAdd(&g_cursor[da.w], 1);
    int p4 = atomicAdd(&g_cursor[db.x], 1);
    int p5 = atomicAdd(&g_cursor[db.y], 1);
    int p6 = atomicAdd(&g_cursor[db.z], 1);
    int p7 = atomicAdd(&g_cursor[db.w], 1);
#define PUT(p, d, s) \
    if ((p) < CAP) g_col[(d) * CAP + (p)] = (s); \
    else { int o = atomicAdd(&g_ovcnt, 1); if (o < OVMAX) g_ov[o] = make_int2((d), (s)); }
    PUT(p0, da.x, sa.x) PUT(p1, da.y, sa.y) PUT(p2, da.z, sa.z) PUT(p3, da.w, sa.w)
    PUT(p4, db.x, sb.x) PUT(p5, db.y, sb.y) PUT(p6, db.z, sb.z) PUT(p7, db.w, sb.w)
#undef PUT
}

// ---------------- 3) fused dinv + xsh = fp16(dinv * emb) ----------------
__global__ void k_dinv_scale(const float* __restrict__ emb) {
    int t = blockIdx.x * 256 + threadIdx.x;          // t < NN*8 (float4 per thread)
    if (t >= NN * (EMB / 4)) return;
    int n = t >> 3;
    float d = rsqrtf((float)(g_cursor[n] + 1));      // +1 self loop
    if ((t & 7) == 0) g_dinv[n] = d;
    float4 v = reinterpret_cast<const float4*>(emb)[t];
    __half2 h0 = __floats2half2_rn(v.x * d, v.y * d);
    __half2 h1 = __floats2half2_rn(v.z * d, v.w * d);
    uint2 st;
    st.x = *reinterpret_cast<unsigned*>(&h0);
    st.y = *reinterpret_cast<unsigned*>(&h1);
    reinterpret_cast<uint2*>(g_xsh)[t] = st;
}

// ---------------- 4) aggregate embeddings: fp16 gather, 8 edges in flight ----------------
// lane = 4*g + l : group g in [0,8) handles edge jb+g; sublane l in [0,4) owns dims [8l, 8l+8).
__global__ void __launch_bounds__(256) k_agg_emb() {
    int w    = (blockIdx.x * 256 + threadIdx.x) >> 5;
    int lane = threadIdx.x & 31;
    int g    = lane >> 2;
    int l    = lane & 3;
    float di = g_dinv[w];
    float a0 = 0.f, a1 = 0.f, a2 = 0.f, a3 = 0.f,
          a4 = 0.f, a5 = 0.f, a6 = 0.f, a7 = 0.f;
    int cnt = min(g_cursor[w], CAP);
    const int* cb = g_col + w * CAP;
    const uint4* xv = reinterpret_cast<const uint4*>(g_xsh);   // 8 halves / uint4, 4 per row
    for (int base = 0; base < cnt; base += 32) {
        int c = cb[base + lane];                     // coalesced 128B
        int m = min(32, cnt - base);                 // warp-uniform
        if (m == 32) {
#pragma unroll
            for (int jb = 0; jb < 32; jb += 8) {
                int   s = __shfl_sync(FULL, c, jb + g);        // per-lane source
                uint4 u = xv[s * 4 + l];
                float2 f0 = __half22float2(*reinterpret_cast<__half2*>(&u.x));
                float2 f1 = __half22float2(*reinterpret_cast<__half2*>(&u.y));
                float2 f2 = __half22float2(*reinterpret_cast<__half2*>(&u.z));
                float2 f3 = __half22float2(*reinterpret_cast<__half2*>(&u.w));
                a0 += f0.x; a1 += f0.y; a2 += f1.x; a3 += f1.y;
                a4 += f2.x; a5 += f2.y; a6 += f3.x; a7 += f3.y;
            }
        } else {
            for (int jb = 0; jb < m; jb += 8) {
                int  j   = jb + g;
                bool act = (j < m);
                int  s   = __shfl_sync(FULL, c, act ? j : 0);
                uint4 u  = xv[s * 4 + l];
                float2 f0 = __half22float2(*reinterpret_cast<__half2*>(&u.x));
                float2 f1 = __half22float2(*reinterpret_cast<__half2*>(&u.y));
                float2 f2 = __half22float2(*reinterpret_cast<__half2*>(&u.z));
                float2 f3 = __half22float2(*reinterpret_cast<__half2*>(&u.w));
                if (act) {
                    a0 += f0.x; a1 += f0.y; a2 += f1.x; a3 += f1.y;
                    a4 += f2.x; a5 += f2.y; a6 += f3.x; a7 += f3.y;
                }
            }
        }
    }
    // reduce across the 8 groups (lanes differing in bits 2,3,4)
#pragma unroll
    for (int off = 4; off <= 16; off <<= 1) {
        a0 += __shfl_xor_sync(FULL, a0, off);
        a1 += __shfl_xor_sync(FULL, a1, off);
        a2 += __shfl_xor_sync(FULL, a2, off);
        a3 += __shfl_xor_sync(FULL, a3, off);
        a4 += __shfl_xor_sync(FULL, a4, off);
        a5 += __shfl_xor_sync(FULL, a5, off);
        a6 += __shfl_xor_sync(FULL, a6, off);
        a7 += __shfl_xor_sync(FULL, a7, off);
    }
    if (g == 0) {
        uint4 u = xv[w * 4 + l];                     // self loop
        float2 f0 = __half22float2(*reinterpret_cast<__half2*>(&u.x));
        float2 f1 = __half22float2(*reinterpret_cast<__half2*>(&u.y));
        float2 f2 = __half22float2(*reinterpret_cast<__half2*>(&u.z));
        float2 f3 = __half22float2(*reinterpret_cast<__half2*>(&u.w));
        a0 = (a0 + f0.x) * di; a1 = (a1 + f0.y) * di;
        a2 = (a2 + f1.x) * di; a3 = (a3 + f1.y) * di;
        a4 = (a4 + f2.x) * di; a5 = (a5 + f2.y) * di;
        a6 = (a6 + f3.x) * di; a7 = (a7 + f3.y) * di;
        float4* dst = reinterpret_cast<float4*>(&g_aggemb[w * EMB + l * 8]);
        dst[0] = make_float4(a0, a1, a2, a3);
        dst[1] = make_float4(a4, a5, a6, a7);
    }
}

// ---------------- 4b) overflow fallback for layer-1 agg (normally empty) ----------------
__global__ void k_ovf1() {
    int nov = min(g_ovcnt, OVMAX);
    int lane = threadIdx.x & 31;
    int warp = (blockIdx.x * 256 + threadIdx.x) >> 5;
    int nw   = (gridDim.x * 256) >> 5;
    for (int i = warp; i < nov; i += nw) {
        int2 e = g_ov[i];                            // (dst, src)
        float v = __half2float(g_xsh[e.y * EMB + lane]);
        atomicAdd(&g_aggemb[e.x * EMB + lane], v * g_dinv[e.x]);
    }
}

// ---------------- 5) GEMM1: h1s = dinv * relu(aggemb @ W1 + b1) -> fp16 ----------------
__global__ void __launch_bounds__(256) k_gemm1(const float* __restrict__ W1,
                                               const float* __restrict__ b1) {
    __shared__ float As[TILE * EMB];     // 8 KB
    int tid  = threadIdx.x;
    int tcol = (tid & 15) * 8;
    int trow = (tid >> 4) * 4;
    int row0 = blockIdx.x * TILE;
    u64 bias[4];
    bias[0] = packf2(__ldg(&b1[tcol]),     __ldg(&b1[tcol + 1]));
    bias[1] = packf2(__ldg(&b1[tcol + 2]), __ldg(&b1[tcol + 3]));
    bias[2] = packf2(__ldg(&b1[tcol + 4]), __ldg(&b1[tcol + 5]));
    bias[3] = packf2(__ldg(&b1[tcol + 6]), __ldg(&b1[tcol + 7]));

#pragma unroll
    for (int i = 0; i < 2; i++) {
        int idx = tid + i * 256;
        int gr  = row0 + (idx >> 3);
        reinterpret_cast<float4*>(As)[idx] = (gr < NN)
            ? reinterpret_cast<const float4*>(g_aggemb)[gr * 8 + (idx & 7)]
            : make_float4(0.f, 0.f, 0.f, 0.f);
    }
    __syncthreads();

    u64 acc[4][4];
#pragma unroll
    for (int r = 0; r < 4; r++)
#pragma unroll
        for (int c = 0; c < 4; c++) acc[r][c] = bias[c];
#pragma unroll
    for (int k = 0; k < EMB; k++) {
        ulonglong2 wa = __ldg(reinterpret_cast<const ulonglong2*>(&W1[k * HID + tcol]));
        ulonglong2 wb = __ldg(reinterpret_cast<const ulonglong2*>(&W1[k * HID + tcol + 4]));
#pragma unroll
        for (int r = 0; r < 4; r++) {
            u64 a = dup2(As[(trow + r) * EMB + k]);
            ffma2(acc[r][0], a, wa.x); ffma2(acc[r][1], a, wa.y);
            ffma2(acc[r][2], a, wb.x); ffma2(acc[r][3], a, wb.y);
        }
    }
#pragma unroll
    for (int r = 0; r < 4; r++) {
        int gr = row0 + trow + r;
        if (gr < NN) {
            float d = g_dinv[gr];
            float2 p0 = unpackf2(acc[r][0]);
            float2 p1 = unpackf2(acc[r][1]);
            float2 p2 = unpackf2(acc[r][2]);
            float2 p3 = unpackf2(acc[r][3]);
            __half2 h0 = __floats2half2_rn(fmaxf(p0.x, 0.f) * d, fmaxf(p0.y, 0.f) * d);
            __half2 h1 = __floats2half2_rn(fmaxf(p1.x, 0.f) * d, fmaxf(p1.y, 0.f) * d);
            __half2 h2 = __floats2half2_rn(fmaxf(p2.x, 0.f) * d, fmaxf(p2.y, 0.f) * d);
            __half2 h3 = __floats2half2_rn(fmaxf(p3.x, 0.f) * d, fmaxf(p3.y, 0.f) * d);
            uint4 st;
            st.x = *reinterpret_cast<unsigned*>(&h0);
            st.y = *reinterpret_cast<unsigned*>(&h1);
            st.z = *reinterpret_cast<unsigned*>(&h2);
            st.w = *reinterpret_cast<unsigned*>(&h3);
            *reinterpret_cast<uint4*>(&g_h1h[gr * HID + tcol]) = st;
        }
    }
}

// ---------------- 6) aggregate h1s: fp16 gather, 2 edges in flight -> fp16 ----------------
// lane = 16*g + l : group g handles edge jb+g; sublane l owns dims [8l, 8l+8).
__global__ void __launch_bounds__(256) k_agg_h1() {
    int w    = (blockIdx.x * 256 + threadIdx.x) >> 5;
    int lane = threadIdx.x & 31;
    int g    = lane >> 4;
    int l    = lane & 15;
    float di = g_dinv[w];
    float a0 = 0.f, a1 = 0.f, a2 = 0.f, a3 = 0.f,
          a4 = 0.f, a5 = 0.f, a6 = 0.f, a7 = 0.f;
    int cnt = min(g_cursor[w], CAP);
    const int* cb = g_col + w * CAP;
    const uint4* hv = reinterpret_cast<const uint4*>(g_h1h);   // 8 halves / uint4
    for (int base = 0; base < cnt; base += 32) {
        int c = cb[base + lane];
        int m = min(32, cnt - base);                 // warp-uniform
        if (m == 32) {
#pragma unroll 4
            for (int jb = 0; jb < 32; jb += 2) {
                int   s = __shfl_sync(FULL, c, jb + g);
                uint4 u = hv[s * 16 + l];
                float2 f0 = __half22float2(*reinterpret_cast<__half2*>(&u.x));
                float2 f1 = __half22float2(*reinterpret_cast<__half2*>(&u.y));
                float2 f2 = __half22float2(*reinterpret_cast<__half2*>(&u.z));
                float2 f3 = __half22float2(*reinterpret_cast<__half2*>(&u.w));
                a0 += f0.x; a1 += f0.y; a2 += f1.x; a3 += f1.y;
                a4 += f2.x; a5 += f2.y; a6 += f3.x; a7 += f3.y;
            }
        } else {
            for (int jb = 0; jb < m; jb += 2) {
                int  j   = jb + g;
                bool act = (j < m);
                int  s   = __shfl_sync(FULL, c, act ? j : 0);
                uint4 u  = hv[s * 16 + l];
                float2 f0 = __half22float2(*reinterpret_cast<__half2*>(&u.x));
                float2 f1 = __half22float2(*reinterpret_cast<__half2*>(&u.y));
                float2 f2 = __half22float2(*reinterpret_cast<__half2*>(&u.z));
                float2 f3 = __half22float2(*reinterpret_cast<__half2*>(&u.w));
                if (act) {
                    a0 += f0.x; a1 += f0.y; a2 += f1.x; a3 += f1.y;
                    a4 += f2.x; a5 += f2.y; a6 += f3.x; a7 += f3.y;
                }
            }
        }
    }
    a0 += __shfl_xor_sync(FULL, a0, 16);
    a1 += __shfl_xor_sync(FULL, a1, 16);
    a2 += __shfl_xor_sync(FULL, a2, 16);
    a3 += __shfl_xor_sync(FULL, a3, 16);
    a4 += __shfl_xor_sync(FULL, a4, 16);
    a5 += __shfl_xor_sync(FULL, a5, 16);
    a6 += __shfl_xor_sync(FULL, a6, 16);
    a7 += __shfl_xor_sync(FULL, a7, 16);
    if (g == 0) {
        uint4 u = hv[w * 16 + l];                    // self loop
        float2 f0 = __half22float2(*reinterpret_cast<__half2*>(&u.x));
        float2 f1 = __half22float2(*reinterpret_cast<__half2*>(&u.y));
        float2 f2 = __half22float2(*reinterpret_cast<__half2*>(&u.z));
        float2 f3 = __half22float2(*reinterpret_cast<__half2*>(&u.w));
        __half2 o0 = __floats2half2_rn((a0 + f0.x) * di, (a1 + f0.y) * di);
        __half2 o1 = __floats2half2_rn((a2 + f1.x) * di, (a3 + f1.y) * di);
        __half2 o2 = __floats2half2_rn((a4 + f2.x) * di, (a5 + f2.y) * di);
        __half2 o3 = __floats2half2_rn((a6 + f3.x) * di, (a7 + f3.y) * di);
        uint4 st;
        st.x = *reinterpret_cast<unsigned*>(&o0);
        st.y = *reinterpret_cast<unsigned*>(&o1);
        st.z = *reinterpret_cast<unsigned*>(&o2);
        st.w = *reinterpret_cast<unsigned*>(&o3);
        *reinterpret_cast<uint4*>(&g_agg2h[w * HID + l * 8]) = st;
    }
}

// ---------------- 6b) overflow fallback for layer-2 agg (normally empty) ----------------
__global__ void k_ovf2() {
    int nov = min(g_ovcnt, OVMAX);
    int lane = threadIdx.x & 31;
    int warp = (blockIdx.x * 256 + threadIdx.x) >> 5;
    int nw   = (gridDim.x * 256) >> 5;
    const uint2* hv = reinterpret_cast<const uint2*>(g_h1h);
    for (int i = warp; i < nov; i += nw) {
        int2 e = g_ov[i];                            // (dst, src)
        float wgt = g_dinv[e.x];
        uint2 u = hv[e.y * 32 + lane];
        float2 ul = __half22float2(*reinterpret_cast<__half2*>(&u.x));
        float2 uh = __half22float2(*reinterpret_cast<__half2*>(&u.y));
        __half2 d0 = __floats2half2_rn(ul.x * wgt, ul.y * wgt);
        __half2 d1 = __floats2half2_rn(uh.x * wgt, uh.y * wgt);
        atomicAdd(reinterpret_cast<__half2*>(&g_agg2h[e.x * HID + lane * 4]),     d0);
        atomicAdd(reinterpret_cast<__half2*>(&g_agg2h[e.x * HID + lane * 4 + 2]), d1);
    }
}

// ---------------- 7) GEMM2: out = agg2h @ W2 + b2, 4x8 FFMA2, fp16 A staging ----------------
__global__ void __launch_bounds__(256) k_gemm2(const float* __restrict__ W2,
                                               const float* __restrict__ b2,
                                               float* __restrict__ out) {
    __shared__ float As[TILE * HID];     // 32 KB
    int tid  = threadIdx.x;
    int tcol = (tid & 15) * 8;
    int trow = (tid >> 4) * 4;
    int row0 = blockIdx.x * TILE;
    u64 bias[4];
    bias[0] = packf2(__ldg(&b2[tcol]),     __ldg(&b2[tcol + 1]));
    bias[1] = packf2(__ldg(&b2[tcol + 2]), __ldg(&b2[tcol + 3]));
    bias[2] = packf2(__ldg(&b2[tcol + 4]), __ldg(&b2[tcol + 5]));
    bias[3] = packf2(__ldg(&b2[tcol + 6]), __ldg(&b2[tcol + 7]));

    // load 64x128 fp16 A tile (1024 uint4, 4 per thread), convert to fp32 smem
    const uint4* av = reinterpret_cast<const uint4*>(g_agg2h);   // 8 halves / uint4
#pragma unroll
    for (int i = 0; i < 4; i++) {
        int idx = tid + i * 256;                     // uint4 index, < 1024
        int gr  = row0 + (idx >> 4);
        uint4 u = (gr < NN) ? av[gr * 16 + (idx & 15)] : make_uint4(0, 0, 0, 0);
        float2 f0 = __half22float2(*reinterpret_cast<__half2*>(&u.x));
        float2 f1 = __half22float2(*reinterpret_cast<__half2*>(&u.y));
        float2 f2 = __half22float2(*reinterpret_cast<__half2*>(&u.z));
        float2 f3 = __half22float2(*reinterpret_cast<__half2*>(&u.w));
        float* dst = &As[(idx >> 4) * HID + (idx & 15) * 8];
        reinterpret_cast<float4*>(dst)[0] = make_float4(f0.x, f0.y, f1.x, f1.y);
        reinterpret_cast<float4*>(dst)[1] = make_float4(f2.x, f2.y, f3.x, f3.y);
    }
    __syncthreads();

    u64 acc[4][4];
#pragma unroll
    for (int r = 0; r < 4; r++)
#pragma unroll
        for (int c = 0; c < 4; c++) acc[r][c] = bias[c];
#pragma unroll 4
    for (int k = 0; k < HID; k++) {
        ulonglong2 wa = __ldg(reinterpret_cast<const ulonglong2*>(&W2[k * HID + tcol]));
        ulonglong2 wb = __ldg(reinterpret_cast<const ulonglong2*>(&W2[k * HID + tcol + 4]));
#pragma unroll
        for (int r = 0; r < 4; r++) {
            u64 a = dup2(As[(trow + r) * HID + k]);
            ffma2(acc[r][0], a, wa.x); ffma2(acc[r][1], a, wa.y);
            ffma2(acc[r][2], a, wb.x); ffma2(acc[r][3], a, wb.y);
        }
    }
#pragma unroll
    for (int r = 0; r < 4; r++) {
        int gr = row0 + trow + r;
        if (gr < NN) {
            float2 p0 = unpackf2(acc[r][0]);
            float2 p1 = unpackf2(acc[r][1]);
            float2 p2 = unpackf2(acc[r][2]);
            float2 p3 = unpackf2(acc[r][3]);
            *reinterpret_cast<float4*>(&out[gr * HID + tcol])     = make_float4(p0.x, p0.y, p1.x, p1.y);
            *reinterpret_cast<float4*>(&out[gr * HID + tcol + 4]) = make_float4(p2.x, p2.y, p3.x, p3.y);
        }
    }
}

// ---------------- host launcher ----------------
extern "C" void kernel_launch(void* const* d_in, const int* in_sizes, int n_in,
                              void* d_out, int out_size) {
    const int*   ei  = (const int*)d_in[1];
    const float* emb = (const float*)d_in[2];
    const float* W1  = (const float*)d_in[3];
    const float* b1  = (const float*)d_in[4];
    const float* W2  = (const float*)d_in[5];
    const float* b2  = (const float*)d_in[6];
    float* out = (float*)d_out;

    const int NT = (NN + TILE - 1) / TILE;           // 782
    k_init       <<<(NN + 255) / 256, 256>>>();
    k_scatter    <<<(ER / 8 + 255) / 256, 256>>>(ei);
    k_dinv_scale <<<(NN * (EMB / 4) + 255) / 256, 256>>>(emb);
    k_agg_emb    <<<(NN * 32) / 256, 256>>>();
    k_ovf1       <<<2, 256>>>();
    k_gemm1      <<<NT, 256>>>(W1, b1);
    k_agg_h1     <<<(NN * 32) / 256, 256>>>();
    k_ovf2       <<<2, 256>>>();
    k_gemm2      <<<NT, 256>>>(W2, b2, out);
}